// round 6
// baseline (speedup 1.0000x reference)
#include <cuda_runtime.h>
#include <math.h>
#include <stdint.h>

#define NN 50000
#define EE 800000

// ---------------- scratch (static device globals; no allocation) ----------------
__device__ float g_z[NN * 160];
__device__ float g_lin[NN * 160];
__device__ float g_h[NN * 128];
__device__ float g_el[NN * 4];
__device__ float g_er[NN * 4];
__device__ float g_bn[256];
__device__ int   g_rowptr[NN + 1];
__device__ int   g_fill[NN];
__device__ int   g_csrc[EE];

// ---------------- CSR build ----------------
__global__ void zero_int_kernel(int* p, int n) {
    int i = blockIdx.x * blockDim.x + threadIdx.x;
    if (i < n) p[i] = 0;
}

__global__ void zero_float_kernel(float* p, int n) {
    int i = blockIdx.x * blockDim.x + threadIdx.x;
    if (i < n) p[i] = 0.f;
}

__global__ void hist_kernel(const int* __restrict__ dst, int* __restrict__ rowptr) {
    int e = blockIdx.x * blockDim.x + threadIdx.x;
    if (e < EE) atomicAdd(&rowptr[dst[e] + 1], 1);
}

// single-block inclusive scan over n ints (n ~ 50001)
__global__ void scan_kernel(int* data, int n) {
    __shared__ int wsum[32];
    int tid = threadIdx.x;
    int lane = tid & 31, wid = tid >> 5;
    int carry = 0;
    for (int base = 0; base < n; base += 1024) {
        int i = base + tid;
        int v = (i < n) ? data[i] : 0;
#pragma unroll
        for (int off = 1; off < 32; off <<= 1) {
            int t = __shfl_up_sync(0xffffffffu, v, off);
            if (lane >= off) v += t;
        }
        if (lane == 31) wsum[wid] = v;
        __syncthreads();
        if (wid == 0) {
            int w = wsum[lane];
#pragma unroll
            for (int off = 1; off < 32; off <<= 1) {
                int t = __shfl_up_sync(0xffffffffu, w, off);
                if (lane >= off) w += t;
            }
            wsum[lane] = w;
        }
        __syncthreads();
        int add = carry + (wid > 0 ? wsum[wid - 1] : 0);
        if (i < n) data[i] = v + add;
        carry += wsum[31];
        __syncthreads();
    }
}

__global__ void copy_int_kernel(int* __restrict__ d, const int* __restrict__ s, int n) {
    int i = blockIdx.x * blockDim.x + threadIdx.x;
    if (i < n) d[i] = s[i];
}

__global__ void scatter_kernel(const int* __restrict__ src, const int* __restrict__ dst,
                               int* __restrict__ fill, int* __restrict__ csrc) {
    int e = blockIdx.x * blockDim.x + threadIdx.x;
    if (e < EE) {
        int pos = atomicAdd(&fill[dst[e]], 1);
        csrc[pos] = src[e];
    }
}

// ---------------- SGEMM: C[N,M] = A[N,K] @ W[K,M], K=128 ----------------
#define BM 64
#define BN 64
#define BK 16

__global__ void sgemm_kernel(const float* __restrict__ A, const float* __restrict__ W,
                             float* __restrict__ C, int Nrows, int K, int M) {
    __shared__ float As[BK][BM];
    __shared__ float Ws[BK][BN];
    int tid = threadIdx.x;
    int tx = tid & 15, ty = tid >> 4;
    int rowBase = blockIdx.x * BM;
    int colBase = blockIdx.y * BN;
    int aRow = tid >> 2;
    int aCol = (tid & 3) * 4;
    int wRow = tid >> 4;
    int wCol = (tid & 15) * 4;

    float acc[4][4];
#pragma unroll
    for (int i = 0; i < 4; i++)
#pragma unroll
        for (int j = 0; j < 4; j++) acc[i][j] = 0.f;

    for (int k0 = 0; k0 < K; k0 += BK) {
        int gr = rowBase + aRow;
        float4 a4 = make_float4(0.f, 0.f, 0.f, 0.f);
        if (gr < Nrows) a4 = *reinterpret_cast<const float4*>(&A[(size_t)gr * K + k0 + aCol]);
        As[aCol + 0][aRow] = a4.x;
        As[aCol + 1][aRow] = a4.y;
        As[aCol + 2][aRow] = a4.z;
        As[aCol + 3][aRow] = a4.w;

        int gc = colBase + wCol;
        float4 w4 = make_float4(0.f, 0.f, 0.f, 0.f);
        const float* wp = &W[(size_t)(k0 + wRow) * M];
        if (gc + 3 < M) {
            w4 = *reinterpret_cast<const float4*>(&wp[gc]);
        } else {
            if (gc + 0 < M) w4.x = wp[gc + 0];
            if (gc + 1 < M) w4.y = wp[gc + 1];
            if (gc + 2 < M) w4.z = wp[gc + 2];
            if (gc + 3 < M) w4.w = wp[gc + 3];
        }
        *reinterpret_cast<float4*>(&Ws[wRow][wCol]) = w4;
        __syncthreads();

#pragma unroll
        for (int k = 0; k < BK; k++) {
            float4 am = *reinterpret_cast<const float4*>(&As[k][ty * 4]);
            float4 wn = *reinterpret_cast<const float4*>(&Ws[k][tx * 4]);
            float amv[4] = {am.x, am.y, am.z, am.w};
            float wnv[4] = {wn.x, wn.y, wn.z, wn.w};
#pragma unroll
            for (int i = 0; i < 4; i++)
#pragma unroll
                for (int j = 0; j < 4; j++) acc[i][j] = fmaf(amv[i], wnv[j], acc[i][j]);
        }
        __syncthreads();
    }

#pragma unroll
    for (int i = 0; i < 4; i++) {
        int r = rowBase + ty * 4 + i;
        if (r < Nrows) {
#pragma unroll
            for (int j = 0; j < 4; j++) {
                int c = colBase + tx * 4 + j;
                if (c < M) C[(size_t)r * M + c] = acc[i][j];
            }
        }
    }
}

// ---------------- el/er: attention logits per (node, head) ----------------
__global__ void eler_kernel(const float* __restrict__ z, const float* __restrict__ al,
                            const float* __restrict__ ar, float* __restrict__ el,
                            float* __restrict__ er, int Dh) {
    int idx = blockIdx.x * blockDim.x + threadIdx.x;
    if (idx >= NN * 4) return;
    int n = idx >> 2, h = idx & 3;
    const float* zp = z + (size_t)n * 4 * Dh + h * Dh;
    const float* alp = al + h * Dh;
    const float* arp = ar + h * Dh;
    float a = 0.f, b = 0.f;
    for (int d = 0; d < Dh; d++) {
        float v = zp[d];
        a = fmaf(v, alp[d], a);
        b = fmaf(v, arp[d], b);
    }
    el[idx] = a;
    er[idx] = b;
}

// ---------------- fused edge-softmax + aggregation (warp per dst node) -------
template <int Dh, bool MEAN>
__global__ void agg_kernel(const int* __restrict__ rowptr, const int* __restrict__ csrc,
                           const float* __restrict__ z, const float* __restrict__ el,
                           const float* __restrict__ er, const float* __restrict__ lin,
                           const float* __restrict__ bc, const float* __restrict__ bias_last,
                           float* __restrict__ out) {
    constexpr int F = 4 * Dh;       // 128 or 160
    constexpr int CH = F / 32;      // 4 or 5
    __shared__ float sh[8][MEAN ? F : 1];
    int lane = threadIdx.x & 31;
    int w = threadIdx.x >> 5;
    int node = blockIdx.x * 8 + w;
    if (node >= NN) return;
    int beg = rowptr[node], end = rowptr[node + 1];

    float er0 = er[node * 4 + 0], er1 = er[node * 4 + 1];
    float er2 = er[node * 4 + 2], er3 = er[node * 4 + 3];

    // phase 1: per-head max of leaky_relu(el[src]+er[dst])
    float m0 = -INFINITY, m1 = -INFINITY, m2 = -INFINITY, m3 = -INFINITY;
    for (int j = beg + lane; j < end; j += 32) {
        int s = csrc[j];
        const float* ep = el + (size_t)s * 4;
        float e;
        e = ep[0] + er0; e = e > 0.f ? e : 0.2f * e; m0 = fmaxf(m0, e);
        e = ep[1] + er1; e = e > 0.f ? e : 0.2f * e; m1 = fmaxf(m1, e);
        e = ep[2] + er2; e = e > 0.f ? e : 0.2f * e; m2 = fmaxf(m2, e);
        e = ep[3] + er3; e = e > 0.f ? e : 0.2f * e; m3 = fmaxf(m3, e);
    }
#pragma unroll
    for (int off = 16; off; off >>= 1) {
        m0 = fmaxf(m0, __shfl_xor_sync(0xffffffffu, m0, off));
        m1 = fmaxf(m1, __shfl_xor_sync(0xffffffffu, m1, off));
        m2 = fmaxf(m2, __shfl_xor_sync(0xffffffffu, m2, off));
        m3 = fmaxf(m3, __shfl_xor_sync(0xffffffffu, m3, off));
    }

    int hidx[CH];
#pragma unroll
    for (int c = 0; c < CH; c++) hidx[c] = (c * 32 + lane) / Dh;

    float acc[CH];
#pragma unroll
    for (int c = 0; c < CH; c++) acc[c] = 0.f;
    float s0 = 0.f, s1 = 0.f, s2 = 0.f, s3 = 0.f;

    // phase 2: all 32 lanes cooperate on each edge (lane owns cols lane+32c)
    for (int j = beg; j < end; j++) {
        int sidx = csrc[j];
        const float* ep = el + (size_t)sidx * 4;
        float e, x0, x1, x2, x3;
        e = ep[0] + er0; e = e > 0.f ? e : 0.2f * e; x0 = __expf(e - m0); s0 += x0;
        e = ep[1] + er1; e = e > 0.f ? e : 0.2f * e; x1 = __expf(e - m1); s1 += x1;
        e = ep[2] + er2; e = e > 0.f ? e : 0.2f * e; x2 = __expf(e - m2); s2 += x2;
        e = ep[3] + er3; e = e > 0.f ? e : 0.2f * e; x3 = __expf(e - m3); s3 += x3;
        const float* zp = z + (size_t)sidx * F;
#pragma unroll
        for (int c = 0; c < CH; c++) {
            int f = c * 32 + lane;
            float xv = hidx[c] == 0 ? x0 : hidx[c] == 1 ? x1 : hidx[c] == 2 ? x2 : x3;
            acc[c] = fmaf(xv, zp[f], acc[c]);
        }
    }

    float i0 = s0 > 0.f ? 1.f / s0 : 1.f;
    float i1 = s1 > 0.f ? 1.f / s1 : 1.f;
    float i2 = s2 > 0.f ? 1.f / s2 : 1.f;
    float i3 = s3 > 0.f ? 1.f / s3 : 1.f;

    if (!MEAN) {
#pragma unroll
        for (int c = 0; c < CH; c++) {
            int f = c * 32 + lane;
            float iv = hidx[c] == 0 ? i0 : hidx[c] == 1 ? i1 : hidx[c] == 2 ? i2 : i3;
            out[(size_t)node * F + f] = fmaf(acc[c], iv, bc[f] + lin[(size_t)node * F + f]);
        }
    } else {
#pragma unroll
        for (int c = 0; c < CH; c++) {
            int f = c * 32 + lane;
            float iv = hidx[c] == 0 ? i0 : hidx[c] == 1 ? i1 : hidx[c] == 2 ? i2 : i3;
            sh[w][f] = fmaf(acc[c], iv, bc[f] + lin[(size_t)node * F + f]);
        }
        __syncwarp();
        for (int cc = lane; cc < Dh; cc += 32) {
            float v = sh[w][cc] + sh[w][Dh + cc] + sh[w][2 * Dh + cc] + sh[w][3 * Dh + cc];
            out[(size_t)node * Dh + cc] = fmaf(v, 0.25f, bias_last[cc]);
        }
    }
}

// ---------------- BatchNorm (stats + apply, F=128) ----------------
__global__ void bn_stats_kernel(const float* __restrict__ x, float* __restrict__ sums) {
    int f = threadIdx.x;  // 128 threads
    float s = 0.f, s2 = 0.f;
    for (int n = blockIdx.x; n < NN; n += gridDim.x) {
        float v = x[(size_t)n * 128 + f];
        s += v;
        s2 = fmaf(v, v, s2);
    }
    atomicAdd(&sums[f], s);
    atomicAdd(&sums[128 + f], s2);
}

__global__ void bn_apply_kernel(float* __restrict__ x, const float* __restrict__ sums,
                                const float* __restrict__ g, const float* __restrict__ b) {
    int idx = blockIdx.x * blockDim.x + threadIdx.x;
    if (idx >= NN * 128) return;
    int f = idx & 127;
    const float invN = 1.f / (float)NN;
    float mu = sums[f] * invN;
    float var = fmaf(-mu, mu, sums[128 + f] * invN);
    float v = (x[idx] - mu) * rsqrtf(var + 1e-5f) * g[f] + b[f];
    x[idx] = fmaxf(v, 0.f);
}

// ---------------- host orchestration ----------------
extern "C" void kernel_launch(void* const* d_in, const int* in_sizes, int n_in,
                              void* d_out, int out_size) {
    (void)in_sizes; (void)n_in; (void)out_size;
    const float* feat = (const float*)d_in[0];
    const int* src = (const int*)d_in[1];
    const int* dst = (const int*)d_in[2];
    const float* Wc[3] = {(const float*)d_in[3], (const float*)d_in[8], (const float*)d_in[13]};
    const float* al[3] = {(const float*)d_in[4], (const float*)d_in[9], (const float*)d_in[14]};
    const float* ar[3] = {(const float*)d_in[5], (const float*)d_in[10], (const float*)d_in[15]};
    const float* bc[3] = {(const float*)d_in[6], (const float*)d_in[11], (const float*)d_in[16]};
    const float* Wl[3] = {(const float*)d_in[7], (const float*)d_in[12], (const float*)d_in[17]};
    const float* gg[2] = {(const float*)d_in[18], (const float*)d_in[20]};
    const float* bb[2] = {(const float*)d_in[19], (const float*)d_in[21]};
    const float* bias_last = (const float*)d_in[22];
    float* out = (float*)d_out;

    void* p;
    cudaGetSymbolAddress(&p, g_z);      float* z = (float*)p;
    cudaGetSymbolAddress(&p, g_lin);    float* lin = (float*)p;
    cudaGetSymbolAddress(&p, g_h);      float* hbuf = (float*)p;
    cudaGetSymbolAddress(&p, g_el);     float* el = (float*)p;
    cudaGetSymbolAddress(&p, g_er);     float* er = (float*)p;
    cudaGetSymbolAddress(&p, g_bn);     float* bn = (float*)p;
    cudaGetSymbolAddress(&p, g_rowptr); int* rowptr = (int*)p;
    cudaGetSymbolAddress(&p, g_fill);   int* fill = (int*)p;
    cudaGetSymbolAddress(&p, g_csrc);   int* csrc = (int*)p;

    // ---- build CSR by destination ----
    zero_int_kernel<<<(NN + 1 + 255) / 256, 256>>>(rowptr, NN + 1);
    hist_kernel<<<(EE + 255) / 256, 256>>>(dst, rowptr);
    scan_kernel<<<1, 1024>>>(rowptr, NN + 1);
    copy_int_kernel<<<(NN + 255) / 256, 256>>>(fill, rowptr, NN);
    scatter_kernel<<<(EE + 255) / 256, 256>>>(src, dst, fill, csrc);

    const float* x = feat;
    for (int L = 0; L < 3; L++) {
        int Dh = (L < 2) ? 32 : 40;
        int M = 4 * Dh;
        dim3 ggrid((NN + BM - 1) / BM, (M + BN - 1) / BN);
        sgemm_kernel<<<ggrid, 256>>>(x, Wc[L], z, NN, 128, M);
        sgemm_kernel<<<ggrid, 256>>>(x, Wl[L], lin, NN, 128, M);
        eler_kernel<<<(NN * 4 + 255) / 256, 256>>>(z, al[L], ar[L], el, er, Dh);
        if (L < 2) {
            agg_kernel<32, false><<<(NN + 7) / 8, 256>>>(rowptr, csrc, z, el, er, lin,
                                                         bc[L], nullptr, hbuf);
            zero_float_kernel<<<1, 256>>>(bn, 256);
            bn_stats_kernel<<<256, 128>>>(hbuf, bn);
            bn_apply_kernel<<<(NN * 128 + 255) / 256, 256>>>(hbuf, bn, gg[L], bb[L]);
            x = hbuf;
        } else {
            agg_kernel<40, true><<<(NN + 7) / 8, 256>>>(rowptr, csrc, z, el, er, lin,
                                                        bc[L], bias_last, out);
        }
    }
}

// round 7
// speedup vs baseline: 1.0523x; 1.0523x over previous
#include <cuda_runtime.h>
#include <math.h>
#include <stdint.h>

#define NN 50000
#define EE 800000

// ---------------- scratch (static device globals; no allocation) ----------------
__device__ float g_z[NN * 160];
__device__ float g_lin[NN * 160];
__device__ float g_h[NN * 128];
__device__ float g_el[NN * 4];
__device__ float g_er[NN * 4];
__device__ float g_bn[256];
__device__ float g_wcat[128 * 320];
__device__ int   g_rowptr[NN + 1];
__device__ int   g_fill[NN];
__device__ int   g_csrc[EE];
__device__ int   g_bsum[256];

// ---------------- small utils ----------------
__global__ void zero_int_kernel(int* p, int n) {
    int i = blockIdx.x * blockDim.x + threadIdx.x;
    if (i < n) p[i] = 0;
}

__global__ void zero_float_kernel(float* p, int n) {
    int i = blockIdx.x * blockDim.x + threadIdx.x;
    if (i < n) p[i] = 0.f;
}

__global__ void hist_kernel(const int* __restrict__ dst, int* __restrict__ rowptr) {
    int e = blockIdx.x * blockDim.x + threadIdx.x;
    if (e < EE) atomicAdd(&rowptr[dst[e] + 1], 1);
}

// ---------------- decoupled 3-phase scan ----------------
// phase 1: per-block inclusive scan of 256 elems; block total to bsum
__global__ void scan_block_kernel(int* __restrict__ data, int n, int* __restrict__ bsum) {
    __shared__ int wsum[8];
    int tid = threadIdx.x;
    int lane = tid & 31, wid = tid >> 5;
    int i = blockIdx.x * 256 + tid;
    int v = (i < n) ? data[i] : 0;
#pragma unroll
    for (int off = 1; off < 32; off <<= 1) {
        int t = __shfl_up_sync(0xffffffffu, v, off);
        if (lane >= off) v += t;
    }
    if (lane == 31) wsum[wid] = v;
    __syncthreads();
    if (wid == 0) {
        int w = (lane < 8) ? wsum[lane] : 0;
#pragma unroll
        for (int off = 1; off < 8; off <<= 1) {
            int t = __shfl_up_sync(0xffffffffu, w, off);
            if (lane >= off) w += t;
        }
        if (lane < 8) wsum[lane] = w;
    }
    __syncthreads();
    int add = (wid > 0) ? wsum[wid - 1] : 0;
    if (i < n) data[i] = v + add;
    if (tid == 255) bsum[blockIdx.x] = v + add;  // block total (tail lanes carry 0)
}

// phase 2: single-block inclusive scan of block sums (nb <= 256)
__global__ void scan_bsum_kernel(int* __restrict__ bsum, int nb) {
    __shared__ int wsum[8];
    int tid = threadIdx.x;
    int lane = tid & 31, wid = tid >> 5;
    int v = (tid < nb) ? bsum[tid] : 0;
#pragma unroll
    for (int off = 1; off < 32; off <<= 1) {
        int t = __shfl_up_sync(0xffffffffu, v, off);
        if (lane >= off) v += t;
    }
    if (lane == 31) wsum[wid] = v;
    __syncthreads();
    if (wid == 0) {
        int w = (lane < 8) ? wsum[lane] : 0;
#pragma unroll
        for (int off = 1; off < 8; off <<= 1) {
            int t = __shfl_up_sync(0xffffffffu, w, off);
            if (lane >= off) w += t;
        }
        if (lane < 8) wsum[lane] = w;
    }
    __syncthreads();
    int add = (wid > 0) ? wsum[wid - 1] : 0;
    if (tid < nb) bsum[tid] = v + add;
}

// phase 3: add exclusive block offsets
__global__ void scan_add_kernel(int* __restrict__ data, int n, const int* __restrict__ bsum) {
    int i = blockIdx.x * 256 + threadIdx.x;
    if (blockIdx.x > 0 && i < n) data[i] += bsum[blockIdx.x - 1];
}

__global__ void copy_int_kernel(int* __restrict__ d, const int* __restrict__ s, int n) {
    int i = blockIdx.x * blockDim.x + threadIdx.x;
    if (i < n) d[i] = s[i];
}

__global__ void scatter_kernel(const int* __restrict__ src, const int* __restrict__ dst,
                               int* __restrict__ fill, int* __restrict__ csrc) {
    int e = blockIdx.x * blockDim.x + threadIdx.x;
    if (e < EE) {
        int pos = atomicAdd(&fill[dst[e]], 1);
        csrc[pos] = src[e];
    }
}

// ---------------- weight pack: Wcat[k][0:M]=Wc[k], Wcat[k][M:2M]=Wl[k] -------
__global__ void pack_w_kernel(const float* __restrict__ Wc, const float* __restrict__ Wl,
                              float* __restrict__ Wcat, int Mh) {
    int idx = blockIdx.x * blockDim.x + threadIdx.x;
    int M2 = 2 * Mh;
    if (idx >= 128 * M2) return;
    int k = idx / M2, j = idx - k * M2;
    Wcat[idx] = (j < Mh) ? Wc[k * Mh + j] : Wl[k * Mh + (j - Mh)];
}

// ---------------- SGEMM 128x128 tile, f32x2 packed FMA, K=128 fixed ----------
// C[N, Mtot] = A[N,128] @ Wcat[128, Mtot]; epilogue splits cols into Z / Lin.
__device__ __forceinline__ void fma_x2(unsigned long long& d, unsigned long long a,
                                       unsigned long long b) {
    asm("fma.rn.f32x2 %0, %1, %2, %0;" : "+l"(d) : "l"(a), "l"(b));
}

__device__ __forceinline__ unsigned long long dup_f32(float a) {
    unsigned long long r;
    asm("mov.b64 %0, {%1, %1};" : "=l"(r) : "r"(__float_as_uint(a)));
    return r;
}

__global__ __launch_bounds__(256, 2)
void sgemm2_kernel(const float* __restrict__ A, const float* __restrict__ W,
                   float* __restrict__ Z, float* __restrict__ Lin,
                   int Nrows, int Mtot, int Mh) {
    __shared__ float As[16][132];   // A transposed: As[k][row], padded
    __shared__ float Ws[16][128];
    int tid = threadIdx.x;
    int tx = tid & 15, ty = tid >> 4;
    int rowBase = blockIdx.x * 128;
    int colBase = blockIdx.y * 128;

    unsigned long long acc[8][4];
#pragma unroll
    for (int i = 0; i < 8; i++)
#pragma unroll
        for (int j = 0; j < 4; j++) acc[i][j] = 0ULL;

    for (int k0 = 0; k0 < 128; k0 += 16) {
        // load A tile: 128 rows x 16 cols (2 float4 per thread)
#pragma unroll
        for (int it = 0; it < 2; it++) {
            int idx = tid + it * 256;          // 0..511
            int r = idx >> 2, v = idx & 3;
            int gr = rowBase + r;
            float4 a4 = make_float4(0.f, 0.f, 0.f, 0.f);
            if (gr < Nrows) a4 = *reinterpret_cast<const float4*>(&A[(size_t)gr * 128 + k0 + v * 4]);
            As[v * 4 + 0][r] = a4.x;
            As[v * 4 + 1][r] = a4.y;
            As[v * 4 + 2][r] = a4.z;
            As[v * 4 + 3][r] = a4.w;
        }
        // load W tile: 16 rows x 128 cols (2 float4 per thread)
#pragma unroll
        for (int it = 0; it < 2; it++) {
            int idx = tid + it * 256;
            int r = idx >> 5, vc = (idx & 31) << 2;
            int gc = colBase + vc;
            float4 w4 = make_float4(0.f, 0.f, 0.f, 0.f);
            if (gc < Mtot) w4 = *reinterpret_cast<const float4*>(&W[(size_t)(k0 + r) * Mtot + gc]);
            *reinterpret_cast<float4*>(&Ws[r][vc]) = w4;
        }
        __syncthreads();

#pragma unroll
        for (int k = 0; k < 16; k++) {
            float4 a0 = *reinterpret_cast<const float4*>(&As[k][ty * 8]);
            float4 a1 = *reinterpret_cast<const float4*>(&As[k][ty * 8 + 4]);
            const unsigned long long* wp =
                reinterpret_cast<const unsigned long long*>(&Ws[k][tx * 8]);
            unsigned long long w0 = wp[0], w1 = wp[1], w2 = wp[2], w3 = wp[3];
            float av[8] = {a0.x, a0.y, a0.z, a0.w, a1.x, a1.y, a1.z, a1.w};
#pragma unroll
            for (int i = 0; i < 8; i++) {
                unsigned long long ap = dup_f32(av[i]);
                fma_x2(acc[i][0], ap, w0);
                fma_x2(acc[i][1], ap, w1);
                fma_x2(acc[i][2], ap, w2);
                fma_x2(acc[i][3], ap, w3);
            }
        }
        __syncthreads();
    }

#pragma unroll
    for (int i = 0; i < 8; i++) {
        int r = rowBase + ty * 8 + i;
        if (r >= Nrows) continue;
#pragma unroll
        for (int j = 0; j < 4; j++) {
            int c = colBase + tx * 8 + j * 2;
            if (c >= Mtot) continue;
            float2 v = *reinterpret_cast<float2*>(&acc[i][j]);
            if (c < Mh)
                *reinterpret_cast<float2*>(&Z[(size_t)r * Mh + c]) = v;
            else
                *reinterpret_cast<float2*>(&Lin[(size_t)r * Mh + (c - Mh)]) = v;
        }
    }
}

// ---------------- el/er: attention logits per (node, head) ----------------
__global__ void eler_kernel(const float* __restrict__ z, const float* __restrict__ al,
                            const float* __restrict__ ar, float* __restrict__ el,
                            float* __restrict__ er, int Dh) {
    int idx = blockIdx.x * blockDim.x + threadIdx.x;
    if (idx >= NN * 4) return;
    int n = idx >> 2, h = idx & 3;
    const float* zp = z + (size_t)n * 4 * Dh + h * Dh;
    const float* alp = al + h * Dh;
    const float* arp = ar + h * Dh;
    float a = 0.f, b = 0.f;
    for (int d = 0; d < Dh; d++) {
        float v = zp[d];
        a = fmaf(v, alp[d], a);
        b = fmaf(v, arp[d], b);
    }
    el[idx] = a;
    er[idx] = b;
}

// ---------------- fused edge-softmax + aggregation (warp per dst node) -------
template <int Dh, bool MEAN>
__global__ void agg_kernel(const int* __restrict__ rowptr, const int* __restrict__ csrc,
                           const float* __restrict__ z, const float* __restrict__ el,
                           const float* __restrict__ er, const float* __restrict__ lin,
                           const float* __restrict__ bc, const float* __restrict__ bias_last,
                           float* __restrict__ out) {
    constexpr int F = 4 * Dh;       // 128 or 160
    constexpr int CH = F / 32;      // 4 or 5
    __shared__ float sh[8][MEAN ? F : 1];
    int lane = threadIdx.x & 31;
    int w = threadIdx.x >> 5;
    int node = blockIdx.x * 8 + w;
    if (node >= NN) return;
    int beg = rowptr[node], end = rowptr[node + 1];

    float er0 = er[node * 4 + 0], er1 = er[node * 4 + 1];
    float er2 = er[node * 4 + 2], er3 = er[node * 4 + 3];

    // phase 1: per-head max of leaky_relu(el[src]+er[dst])
    float m0 = -INFINITY, m1 = -INFINITY, m2 = -INFINITY, m3 = -INFINITY;
    for (int j = beg + lane; j < end; j += 32) {
        int s = csrc[j];
        const float* ep = el + (size_t)s * 4;
        float e;
        e = ep[0] + er0; e = e > 0.f ? e : 0.2f * e; m0 = fmaxf(m0, e);
        e = ep[1] + er1; e = e > 0.f ? e : 0.2f * e; m1 = fmaxf(m1, e);
        e = ep[2] + er2; e = e > 0.f ? e : 0.2f * e; m2 = fmaxf(m2, e);
        e = ep[3] + er3; e = e > 0.f ? e : 0.2f * e; m3 = fmaxf(m3, e);
    }
#pragma unroll
    for (int off = 16; off; off >>= 1) {
        m0 = fmaxf(m0, __shfl_xor_sync(0xffffffffu, m0, off));
        m1 = fmaxf(m1, __shfl_xor_sync(0xffffffffu, m1, off));
        m2 = fmaxf(m2, __shfl_xor_sync(0xffffffffu, m2, off));
        m3 = fmaxf(m3, __shfl_xor_sync(0xffffffffu, m3, off));
    }

    int hidx[CH];
#pragma unroll
    for (int c = 0; c < CH; c++) hidx[c] = (c * 32 + lane) / Dh;

    float acc[CH];
#pragma unroll
    for (int c = 0; c < CH; c++) acc[c] = 0.f;
    float s0 = 0.f, s1 = 0.f, s2 = 0.f, s3 = 0.f;

    // phase 2: all 32 lanes cooperate on each edge (lane owns cols lane+32c)
    for (int j = beg; j < end; j++) {
        int sidx = csrc[j];
        const float* ep = el + (size_t)sidx * 4;
        float e, x0, x1, x2, x3;
        e = ep[0] + er0; e = e > 0.f ? e : 0.2f * e; x0 = __expf(e - m0); s0 += x0;
        e = ep[1] + er1; e = e > 0.f ? e : 0.2f * e; x1 = __expf(e - m1); s1 += x1;
        e = ep[2] + er2; e = e > 0.f ? e : 0.2f * e; x2 = __expf(e - m2); s2 += x2;
        e = ep[3] + er3; e = e > 0.f ? e : 0.2f * e; x3 = __expf(e - m3); s3 += x3;
        const float* zp = z + (size_t)sidx * F;
#pragma unroll
        for (int c = 0; c < CH; c++) {
            int f = c * 32 + lane;
            float xv = hidx[c] == 0 ? x0 : hidx[c] == 1 ? x1 : hidx[c] == 2 ? x2 : x3;
            acc[c] = fmaf(xv, zp[f], acc[c]);
        }
    }

    float i0 = s0 > 0.f ? 1.f / s0 : 1.f;
    float i1 = s1 > 0.f ? 1.f / s1 : 1.f;
    float i2 = s2 > 0.f ? 1.f / s2 : 1.f;
    float i3 = s3 > 0.f ? 1.f / s3 : 1.f;

    if (!MEAN) {
#pragma unroll
        for (int c = 0; c < CH; c++) {
            int f = c * 32 + lane;
            float iv = hidx[c] == 0 ? i0 : hidx[c] == 1 ? i1 : hidx[c] == 2 ? i2 : i3;
            out[(size_t)node * F + f] = fmaf(acc[c], iv, bc[f] + lin[(size_t)node * F + f]);
        }
    } else {
#pragma unroll
        for (int c = 0; c < CH; c++) {
            int f = c * 32 + lane;
            float iv = hidx[c] == 0 ? i0 : hidx[c] == 1 ? i1 : hidx[c] == 2 ? i2 : i3;
            sh[w][f] = fmaf(acc[c], iv, bc[f] + lin[(size_t)node * F + f]);
        }
        __syncwarp();
        for (int cc = lane; cc < Dh; cc += 32) {
            float v = sh[w][cc] + sh[w][Dh + cc] + sh[w][2 * Dh + cc] + sh[w][3 * Dh + cc];
            out[(size_t)node * Dh + cc] = fmaf(v, 0.25f, bias_last[cc]);
        }
    }
}

// ---------------- BatchNorm (stats + apply, F=128) ----------------
__global__ void bn_stats_kernel(const float* __restrict__ x, float* __restrict__ sums) {
    int f = threadIdx.x;  // 128 threads
    float s = 0.f, s2 = 0.f;
    for (int n = blockIdx.x; n < NN; n += gridDim.x) {
        float v = x[(size_t)n * 128 + f];
        s += v;
        s2 = fmaf(v, v, s2);
    }
    atomicAdd(&sums[f], s);
    atomicAdd(&sums[128 + f], s2);
}

__global__ void bn_apply_kernel(float* __restrict__ x, const float* __restrict__ sums,
                                const float* __restrict__ g, const float* __restrict__ b) {
    int idx = blockIdx.x * blockDim.x + threadIdx.x;
    if (idx >= NN * 128) return;
    int f = idx & 127;
    const float invN = 1.f / (float)NN;
    float mu = sums[f] * invN;
    float var = fmaf(-mu, mu, sums[128 + f] * invN);
    float v = (x[idx] - mu) * rsqrtf(var + 1e-5f) * g[f] + b[f];
    x[idx] = fmaxf(v, 0.f);
}

// ---------------- host orchestration ----------------
extern "C" void kernel_launch(void* const* d_in, const int* in_sizes, int n_in,
                              void* d_out, int out_size) {
    (void)in_sizes; (void)n_in; (void)out_size;
    const float* feat = (const float*)d_in[0];
    const int* src = (const int*)d_in[1];
    const int* dst = (const int*)d_in[2];
    const float* Wc[3] = {(const float*)d_in[3], (const float*)d_in[8], (const float*)d_in[13]};
    const float* al[3] = {(const float*)d_in[4], (const float*)d_in[9], (const float*)d_in[14]};
    const float* ar[3] = {(const float*)d_in[5], (const float*)d_in[10], (const float*)d_in[15]};
    const float* bc[3] = {(const float*)d_in[6], (const float*)d_in[11], (const float*)d_in[16]};
    const float* Wl[3] = {(const float*)d_in[7], (const float*)d_in[12], (const float*)d_in[17]};
    const float* gg[2] = {(const float*)d_in[18], (const float*)d_in[20]};
    const float* bb[2] = {(const float*)d_in[19], (const float*)d_in[21]};
    const float* bias_last = (const float*)d_in[22];
    float* out = (float*)d_out;

    void* p;
    cudaGetSymbolAddress(&p, g_z);      float* z = (float*)p;
    cudaGetSymbolAddress(&p, g_lin);    float* lin = (float*)p;
    cudaGetSymbolAddress(&p, g_h);      float* hbuf = (float*)p;
    cudaGetSymbolAddress(&p, g_el);     float* el = (float*)p;
    cudaGetSymbolAddress(&p, g_er);     float* er = (float*)p;
    cudaGetSymbolAddress(&p, g_bn);     float* bn = (float*)p;
    cudaGetSymbolAddress(&p, g_wcat);   float* wcat = (float*)p;
    cudaGetSymbolAddress(&p, g_rowptr); int* rowptr = (int*)p;
    cudaGetSymbolAddress(&p, g_fill);   int* fill = (int*)p;
    cudaGetSymbolAddress(&p, g_csrc);   int* csrc = (int*)p;
    cudaGetSymbolAddress(&p, g_bsum);   int* bsum = (int*)p;

    // ---- build CSR by destination ----
    const int NSCAN = NN + 1;
    const int NB = (NSCAN + 255) / 256;  // 196
    zero_int_kernel<<<(NSCAN + 255) / 256, 256>>>(rowptr, NSCAN);
    hist_kernel<<<(EE + 255) / 256, 256>>>(dst, rowptr);
    scan_block_kernel<<<NB, 256>>>(rowptr, NSCAN, bsum);
    scan_bsum_kernel<<<1, 256>>>(bsum, NB);
    scan_add_kernel<<<NB, 256>>>(rowptr, NSCAN, bsum);
    copy_int_kernel<<<(NN + 255) / 256, 256>>>(fill, rowptr, NN);
    scatter_kernel<<<(EE + 255) / 256, 256>>>(src, dst, fill, csrc);

    const float* x = feat;
    for (int L = 0; L < 3; L++) {
        int Dh = (L < 2) ? 32 : 40;
        int M = 4 * Dh;          // 128 or 160
        int Mtot = 2 * M;        // 256 or 320
        pack_w_kernel<<<(128 * Mtot + 255) / 256, 256>>>(Wc[L], Wl[L], wcat, M);
        dim3 ggrid((NN + 127) / 128, (Mtot + 127) / 128);
        sgemm2_kernel<<<ggrid, 256>>>(x, wcat, z, lin, NN, Mtot, M);
        eler_kernel<<<(NN * 4 + 255) / 256, 256>>>(z, al[L], ar[L], el, er, Dh);
        if (L < 2) {
            agg_kernel<32, false><<<(NN + 7) / 8, 256>>>(rowptr, csrc, z, el, er, lin,
                                                         bc[L], nullptr, hbuf);
            zero_float_kernel<<<1, 256>>>(bn, 256);
            bn_stats_kernel<<<256, 128>>>(hbuf, bn);
            bn_apply_kernel<<<(NN * 128 + 255) / 256, 256>>>(hbuf, bn, gg[L], bb[L]);
            x = hbuf;
        } else {
            agg_kernel<40, true><<<(NN + 7) / 8, 256>>>(rowptr, csrc, z, el, er, lin,
                                                        bc[L], bias_last, out);
        }
    }
}

// round 8
// speedup vs baseline: 1.0949x; 1.0405x over previous
#include <cuda_runtime.h>
#include <math.h>
#include <stdint.h>

#define NN 50000
#define EE 800000

// ---------------- scratch (static device globals; no allocation) ----------------
__device__ float g_z[NN * 160];
__device__ float g_lin[NN * 160];
__device__ float g_h[NN * 128];
__device__ float g_el[NN * 4];
__device__ float g_er[NN * 4];
__device__ float g_bn[512];              // layer0: [0,256), layer1: [256,512)
__device__ float g_wcat[128 * 832];      // packed [Wc0|Wl0][Wc1|Wl1][Wc2|Wl2]
__device__ int   g_rowptr[NN + 1];
__device__ int   g_fill[NN];
__device__ int   g_csrc[EE];
__device__ int   g_bsum[256];

// ---------------- small utils ----------------
__global__ void zero_int_kernel(int* p, int n) {
    int i = blockIdx.x * blockDim.x + threadIdx.x;
    if (i < n) p[i] = 0;
}

__global__ void hist_kernel(const int* __restrict__ dst, int* __restrict__ rowptr) {
    int e = blockIdx.x * blockDim.x + threadIdx.x;
    if (e < EE) atomicAdd(&rowptr[dst[e] + 1], 1);
}

// ---------------- decoupled 3-phase scan ----------------
__global__ void scan_block_kernel(int* __restrict__ data, int n, int* __restrict__ bsum) {
    __shared__ int wsum[8];
    int tid = threadIdx.x;
    int lane = tid & 31, wid = tid >> 5;
    int i = blockIdx.x * 256 + tid;
    int v = (i < n) ? data[i] : 0;
#pragma unroll
    for (int off = 1; off < 32; off <<= 1) {
        int t = __shfl_up_sync(0xffffffffu, v, off);
        if (lane >= off) v += t;
    }
    if (lane == 31) wsum[wid] = v;
    __syncthreads();
    if (wid == 0) {
        int w = (lane < 8) ? wsum[lane] : 0;
#pragma unroll
        for (int off = 1; off < 8; off <<= 1) {
            int t = __shfl_up_sync(0xffffffffu, w, off);
            if (lane >= off) w += t;
        }
        if (lane < 8) wsum[lane] = w;
    }
    __syncthreads();
    int add = (wid > 0) ? wsum[wid - 1] : 0;
    if (i < n) data[i] = v + add;
    if (tid == 255) bsum[blockIdx.x] = v + add;
}

__global__ void scan_bsum_kernel(int* __restrict__ bsum, int nb) {
    __shared__ int wsum[8];
    int tid = threadIdx.x;
    int lane = tid & 31, wid = tid >> 5;
    int v = (tid < nb) ? bsum[tid] : 0;
#pragma unroll
    for (int off = 1; off < 32; off <<= 1) {
        int t = __shfl_up_sync(0xffffffffu, v, off);
        if (lane >= off) v += t;
    }
    if (lane == 31) wsum[wid] = v;
    __syncthreads();
    if (wid == 0) {
        int w = (lane < 8) ? wsum[lane] : 0;
#pragma unroll
        for (int off = 1; off < 8; off <<= 1) {
            int t = __shfl_up_sync(0xffffffffu, w, off);
            if (lane >= off) w += t;
        }
        if (lane < 8) wsum[lane] = w;
    }
    __syncthreads();
    int add = (wid > 0) ? wsum[wid - 1] : 0;
    if (tid < nb) bsum[tid] = v + add;
}

__global__ void scan_add_kernel(int* __restrict__ data, int n, const int* __restrict__ bsum) {
    int i = blockIdx.x * 256 + threadIdx.x;
    if (blockIdx.x > 0 && i < n) data[i] += bsum[blockIdx.x - 1];
}

__global__ void copy_int_kernel(int* __restrict__ d, const int* __restrict__ s, int n) {
    int i = blockIdx.x * blockDim.x + threadIdx.x;
    if (i < n) d[i] = s[i];
}

__global__ void scatter_kernel(const int* __restrict__ src, const int* __restrict__ dst,
                               int* __restrict__ fill, int* __restrict__ csrc) {
    int e = blockIdx.x * blockDim.x + threadIdx.x;
    if (e < EE) {
        int pos = atomicAdd(&fill[dst[e]], 1);
        csrc[pos] = src[e];
    }
}

// ---------------- pack all weights once + zero BN buffers ----------------
__global__ void pack_all_kernel(const float* __restrict__ Wc0, const float* __restrict__ Wl0,
                                const float* __restrict__ Wc1, const float* __restrict__ Wl1,
                                const float* __restrict__ Wc2, const float* __restrict__ Wl2,
                                float* __restrict__ wcat, float* __restrict__ bn) {
    int idx = blockIdx.x * blockDim.x + threadIdx.x;
    if (idx < 512) { bn[idx] = 0.f; }
    int id = idx - 512;
    if (id < 0 || id >= 128 * 832) return;
    if (id < 32768) {
        int k = id >> 8, j = id & 255;
        wcat[id] = (j < 128) ? Wc0[k * 128 + j] : Wl0[k * 128 + (j - 128)];
    } else if (id < 65536) {
        int id2 = id - 32768;
        int k = id2 >> 8, j = id2 & 255;
        wcat[id] = (j < 128) ? Wc1[k * 128 + j] : Wl1[k * 128 + (j - 128)];
    } else {
        int id3 = id - 65536;
        int k = id3 / 320, j = id3 - k * 320;
        wcat[id] = (j < 160) ? Wc2[k * 160 + j] : Wl2[k * 160 + (j - 160)];
    }
}

// ---------------- SGEMM 128x128 tile, f32x2 packed FMA, K=128 fixed ----------
// C[N, Mtot] = act(A)[N,128] @ Wcat[128, Mtot]; epilogue splits cols Z / Lin.
// APPLY_BN: A element = relu(raw*scale[f] + shift[f]) with per-feature BN affine.
__device__ __forceinline__ void fma_x2(unsigned long long& d, unsigned long long a,
                                       unsigned long long b) {
    asm("fma.rn.f32x2 %0, %1, %2, %0;" : "+l"(d) : "l"(a), "l"(b));
}

__device__ __forceinline__ unsigned long long dup_f32(float a) {
    unsigned long long r;
    asm("mov.b64 %0, {%1, %1};" : "=l"(r) : "r"(__float_as_uint(a)));
    return r;
}

template <bool APPLY_BN>
__global__ __launch_bounds__(256, 2)
void sgemm2_kernel(const float* __restrict__ A, const float* __restrict__ W,
                   float* __restrict__ Z, float* __restrict__ Lin,
                   int Nrows, int Mtot, int Mh,
                   const float* __restrict__ sums, const float* __restrict__ gamma,
                   const float* __restrict__ beta) {
    __shared__ float As[16][132];
    __shared__ float Ws[16][128];
    __shared__ float scale_s[128], shift_s[128];
    int tid = threadIdx.x;
    int tx = tid & 15, ty = tid >> 4;
    int rowBase = blockIdx.x * 128;
    int colBase = blockIdx.y * 128;

    if (APPLY_BN) {
        if (tid < 128) {
            const float invN = 1.f / (float)NN;
            float mu = sums[tid] * invN;
            float var = fmaf(-mu, mu, sums[128 + tid] * invN);
            float s = gamma[tid] * rsqrtf(var + 1e-5f);
            scale_s[tid] = s;
            shift_s[tid] = fmaf(-mu, s, beta[tid]);
        }
        __syncthreads();
    }

    unsigned long long acc[8][4];
#pragma unroll
    for (int i = 0; i < 8; i++)
#pragma unroll
        for (int j = 0; j < 4; j++) acc[i][j] = 0ULL;

    for (int k0 = 0; k0 < 128; k0 += 16) {
#pragma unroll
        for (int it = 0; it < 2; it++) {
            int idx = tid + it * 256;
            int r = idx >> 2, v = idx & 3;
            int gr = rowBase + r;
            float4 a4 = make_float4(0.f, 0.f, 0.f, 0.f);
            if (gr < Nrows) a4 = *reinterpret_cast<const float4*>(&A[(size_t)gr * 128 + k0 + v * 4]);
            if (APPLY_BN) {
                int f = k0 + v * 4;
                a4.x = fmaxf(fmaf(a4.x, scale_s[f + 0], shift_s[f + 0]), 0.f);
                a4.y = fmaxf(fmaf(a4.y, scale_s[f + 1], shift_s[f + 1]), 0.f);
                a4.z = fmaxf(fmaf(a4.z, scale_s[f + 2], shift_s[f + 2]), 0.f);
                a4.w = fmaxf(fmaf(a4.w, scale_s[f + 3], shift_s[f + 3]), 0.f);
            }
            As[v * 4 + 0][r] = a4.x;
            As[v * 4 + 1][r] = a4.y;
            As[v * 4 + 2][r] = a4.z;
            As[v * 4 + 3][r] = a4.w;
        }
#pragma unroll
        for (int it = 0; it < 2; it++) {
            int idx = tid + it * 256;
            int r = idx >> 5, vc = (idx & 31) << 2;
            int gc = colBase + vc;
            float4 w4 = make_float4(0.f, 0.f, 0.f, 0.f);
            if (gc < Mtot) w4 = *reinterpret_cast<const float4*>(&W[(size_t)(k0 + r) * Mtot + gc]);
            *reinterpret_cast<float4*>(&Ws[r][vc]) = w4;
        }
        __syncthreads();

#pragma unroll
        for (int k = 0; k < 16; k++) {
            float4 a0 = *reinterpret_cast<const float4*>(&As[k][ty * 8]);
            float4 a1 = *reinterpret_cast<const float4*>(&As[k][ty * 8 + 4]);
            const unsigned long long* wp =
                reinterpret_cast<const unsigned long long*>(&Ws[k][tx * 8]);
            unsigned long long w0 = wp[0], w1 = wp[1], w2 = wp[2], w3 = wp[3];
            float av[8] = {a0.x, a0.y, a0.z, a0.w, a1.x, a1.y, a1.z, a1.w};
#pragma unroll
            for (int i = 0; i < 8; i++) {
                unsigned long long ap = dup_f32(av[i]);
                fma_x2(acc[i][0], ap, w0);
                fma_x2(acc[i][1], ap, w1);
                fma_x2(acc[i][2], ap, w2);
                fma_x2(acc[i][3], ap, w3);
            }
        }
        __syncthreads();
    }

#pragma unroll
    for (int i = 0; i < 8; i++) {
        int r = rowBase + ty * 8 + i;
        if (r >= Nrows) continue;
#pragma unroll
        for (int j = 0; j < 4; j++) {
            int c = colBase + tx * 8 + j * 2;
            if (c >= Mtot) continue;
            float2 v = *reinterpret_cast<float2*>(&acc[i][j]);
            if (c < Mh)
                *reinterpret_cast<float2*>(&Z[(size_t)r * Mh + c]) = v;
            else
                *reinterpret_cast<float2*>(&Lin[(size_t)r * Mh + (c - Mh)]) = v;
        }
    }
}

// ---------------- el/er: attention logits per (node, head) ----------------
__global__ void eler_kernel(const float* __restrict__ z, const float* __restrict__ al,
                            const float* __restrict__ ar, float* __restrict__ el,
                            float* __restrict__ er, int Dh) {
    int idx = blockIdx.x * blockDim.x + threadIdx.x;
    if (idx >= NN * 4) return;
    int n = idx >> 2, h = idx & 3;
    const float* zp = z + (size_t)n * 4 * Dh + h * Dh;
    const float* alp = al + h * Dh;
    const float* arp = ar + h * Dh;
    float a = 0.f, b = 0.f;
    for (int d = 0; d < Dh; d++) {
        float v = zp[d];
        a = fmaf(v, alp[d], a);
        b = fmaf(v, arp[d], b);
    }
    el[idx] = a;
    er[idx] = b;
}

// ---------------- fused edge-softmax + aggregation (warp per dst node) -------
// Vectorized: lane owns feature cols [4*lane, 4*lane+4); for F=160 lanes 0..7
// additionally own [128+4*lane, 128+4*lane+4) (head 3). A 4-col chunk never
// straddles a head boundary for Dh in {32, 40}.
template <int Dh, bool MEAN>
__global__ void agg_kernel(const int* __restrict__ rowptr, const int* __restrict__ csrc,
                           const float* __restrict__ z, const float* __restrict__ el,
                           const float* __restrict__ er, const float* __restrict__ lin,
                           const float* __restrict__ bc, const float* __restrict__ bias_last,
                           float* __restrict__ out) {
    constexpr int F = 4 * Dh;
    constexpr bool EXTRA = (F == 160);
    __shared__ float sh[8][MEAN ? F : 1];
    int lane = threadIdx.x & 31;
    int w = threadIdx.x >> 5;
    int node = blockIdx.x * 8 + w;
    if (node >= NN) return;
    int beg = rowptr[node], end = rowptr[node + 1];

    float4 er4 = *reinterpret_cast<const float4*>(er + (size_t)node * 4);

    // phase 1: per-head max of leaky_relu(el[src]+er[dst])
    float m0 = -INFINITY, m1 = -INFINITY, m2 = -INFINITY, m3 = -INFINITY;
    for (int j = beg + lane; j < end; j += 32) {
        int s = csrc[j];
        float4 e4 = *reinterpret_cast<const float4*>(el + (size_t)s * 4);
        float e;
        e = e4.x + er4.x; e = e > 0.f ? e : 0.2f * e; m0 = fmaxf(m0, e);
        e = e4.y + er4.y; e = e > 0.f ? e : 0.2f * e; m1 = fmaxf(m1, e);
        e = e4.z + er4.z; e = e > 0.f ? e : 0.2f * e; m2 = fmaxf(m2, e);
        e = e4.w + er4.w; e = e > 0.f ? e : 0.2f * e; m3 = fmaxf(m3, e);
    }
#pragma unroll
    for (int off = 16; off; off >>= 1) {
        m0 = fmaxf(m0, __shfl_xor_sync(0xffffffffu, m0, off));
        m1 = fmaxf(m1, __shfl_xor_sync(0xffffffffu, m1, off));
        m2 = fmaxf(m2, __shfl_xor_sync(0xffffffffu, m2, off));
        m3 = fmaxf(m3, __shfl_xor_sync(0xffffffffu, m3, off));
    }

    const int h0 = (lane * 4) / Dh;   // head of this lane's primary chunk

    float4 acc0 = make_float4(0.f, 0.f, 0.f, 0.f);
    float4 acc1 = make_float4(0.f, 0.f, 0.f, 0.f);
    float s0 = 0.f, s1 = 0.f, s2 = 0.f, s3 = 0.f;

    // phase 2: all 32 lanes cooperate on each edge
    for (int j = beg; j < end; j++) {
        int sidx = csrc[j];
        float4 e4 = *reinterpret_cast<const float4*>(el + (size_t)sidx * 4);
        float e, x0, x1, x2, x3;
        e = e4.x + er4.x; e = e > 0.f ? e : 0.2f * e; x0 = __expf(e - m0); s0 += x0;
        e = e4.y + er4.y; e = e > 0.f ? e : 0.2f * e; x1 = __expf(e - m1); s1 += x1;
        e = e4.z + er4.z; e = e > 0.f ? e : 0.2f * e; x2 = __expf(e - m2); s2 += x2;
        e = e4.w + er4.w; e = e > 0.f ? e : 0.2f * e; x3 = __expf(e - m3); s3 += x3;
        const float4* zp = reinterpret_cast<const float4*>(z + (size_t)sidx * F);
        float4 zv = zp[lane];
        float xv = h0 == 0 ? x0 : h0 == 1 ? x1 : h0 == 2 ? x2 : x3;
        acc0.x = fmaf(xv, zv.x, acc0.x);
        acc0.y = fmaf(xv, zv.y, acc0.y);
        acc0.z = fmaf(xv, zv.z, acc0.z);
        acc0.w = fmaf(xv, zv.w, acc0.w);
        if (EXTRA && lane < 8) {
            float4 zv1 = zp[32 + lane];
            acc1.x = fmaf(x3, zv1.x, acc1.x);
            acc1.y = fmaf(x3, zv1.y, acc1.y);
            acc1.z = fmaf(x3, zv1.z, acc1.z);
            acc1.w = fmaf(x3, zv1.w, acc1.w);
        }
    }

    float i0 = s0 > 0.f ? 1.f / s0 : 1.f;
    float i1 = s1 > 0.f ? 1.f / s1 : 1.f;
    float i2 = s2 > 0.f ? 1.f / s2 : 1.f;
    float i3 = s3 > 0.f ? 1.f / s3 : 1.f;
    float iv0 = h0 == 0 ? i0 : h0 == 1 ? i1 : h0 == 2 ? i2 : i3;

    int f = lane * 4;
    if (!MEAN) {
        float4 l4 = *reinterpret_cast<const float4*>(lin + (size_t)node * F + f);
        float4 b4 = *reinterpret_cast<const float4*>(bc + f);
        float4 r;
        r.x = fmaf(acc0.x, iv0, b4.x + l4.x);
        r.y = fmaf(acc0.y, iv0, b4.y + l4.y);
        r.z = fmaf(acc0.z, iv0, b4.z + l4.z);
        r.w = fmaf(acc0.w, iv0, b4.w + l4.w);
        *reinterpret_cast<float4*>(out + (size_t)node * F + f) = r;
        if (EXTRA && lane < 8) {
            int f1 = 128 + lane * 4;
            float4 l41 = *reinterpret_cast<const float4*>(lin + (size_t)node * F + f1);
            float4 b41 = *reinterpret_cast<const float4*>(bc + f1);
            float4 r1;
            r1.x = fmaf(acc1.x, i3, b41.x + l41.x);
            r1.y = fmaf(acc1.y, i3, b41.y + l41.y);
            r1.z = fmaf(acc1.z, i3, b41.z + l41.z);
            r1.w = fmaf(acc1.w, i3, b41.w + l41.w);
            *reinterpret_cast<float4*>(out + (size_t)node * F + f1) = r1;
        }
    } else {
        float4 l4 = *reinterpret_cast<const float4*>(lin + (size_t)node * F + f);
        float4 b4 = *reinterpret_cast<const float4*>(bc + f);
        sh[w][f + 0] = fmaf(acc0.x, iv0, b4.x + l4.x);
        sh[w][f + 1] = fmaf(acc0.y, iv0, b4.y + l4.y);
        sh[w][f + 2] = fmaf(acc0.z, iv0, b4.z + l4.z);
        sh[w][f + 3] = fmaf(acc0.w, iv0, b4.w + l4.w);
        if (EXTRA && lane < 8) {
            int f1 = 128 + lane * 4;
            float4 l41 = *reinterpret_cast<const float4*>(lin + (size_t)node * F + f1);
            float4 b41 = *reinterpret_cast<const float4*>(bc + f1);
            sh[w][f1 + 0] = fmaf(acc1.x, i3, b41.x + l41.x);
            sh[w][f1 + 1] = fmaf(acc1.y, i3, b41.y + l41.y);
            sh[w][f1 + 2] = fmaf(acc1.z, i3, b41.z + l41.z);
            sh[w][f1 + 3] = fmaf(acc1.w, i3, b41.w + l41.w);
        }
        __syncwarp();
        for (int cc = lane; cc < Dh; cc += 32) {
            float v = sh[w][cc] + sh[w][Dh + cc] + sh[w][2 * Dh + cc] + sh[w][3 * Dh + cc];
            out[(size_t)node * Dh + cc] = fmaf(v, 0.25f, bias_last[cc]);
        }
    }
}

// ---------------- BatchNorm stats (sum / sumsq per feature, F=128) ----------
__global__ void bn_stats_kernel(const float* __restrict__ x, float* __restrict__ sums) {
    int f = threadIdx.x;  // 128 threads
    float s = 0.f, s2 = 0.f;
    for (int n = blockIdx.x; n < NN; n += gridDim.x) {
        float v = x[(size_t)n * 128 + f];
        s += v;
        s2 = fmaf(v, v, s2);
    }
    atomicAdd(&sums[f], s);
    atomicAdd(&sums[128 + f], s2);
}

// ---------------- host orchestration ----------------
extern "C" void kernel_launch(void* const* d_in, const int* in_sizes, int n_in,
                              void* d_out, int out_size) {
    (void)in_sizes; (void)n_in; (void)out_size;
    const float* feat = (const float*)d_in[0];
    const int* src = (const int*)d_in[1];
    const int* dst = (const int*)d_in[2];
    const float* Wc[3] = {(const float*)d_in[3], (const float*)d_in[8], (const float*)d_in[13]};
    const float* al[3] = {(const float*)d_in[4], (const float*)d_in[9], (const float*)d_in[14]};
    const float* ar[3] = {(const float*)d_in[5], (const float*)d_in[10], (const float*)d_in[15]};
    const float* bc[3] = {(const float*)d_in[6], (const float*)d_in[11], (const float*)d_in[16]};
    const float* Wl[3] = {(const float*)d_in[7], (const float*)d_in[12], (const float*)d_in[17]};
    const float* gg[2] = {(const float*)d_in[18], (const float*)d_in[20]};
    const float* bb[2] = {(const float*)d_in[19], (const float*)d_in[21]};
    const float* bias_last = (const float*)d_in[22];
    float* out = (float*)d_out;

    void* p;
    cudaGetSymbolAddress(&p, g_z);      float* z = (float*)p;
    cudaGetSymbolAddress(&p, g_lin);    float* lin = (float*)p;
    cudaGetSymbolAddress(&p, g_h);      float* hbuf = (float*)p;
    cudaGetSymbolAddress(&p, g_el);     float* el = (float*)p;
    cudaGetSymbolAddress(&p, g_er);     float* er = (float*)p;
    cudaGetSymbolAddress(&p, g_bn);     float* bn = (float*)p;
    cudaGetSymbolAddress(&p, g_wcat);   float* wcat = (float*)p;
    cudaGetSymbolAddress(&p, g_rowptr); int* rowptr = (int*)p;
    cudaGetSymbolAddress(&p, g_fill);   int* fill = (int*)p;
    cudaGetSymbolAddress(&p, g_csrc);   int* csrc = (int*)p;
    cudaGetSymbolAddress(&p, g_bsum);   int* bsum = (int*)p;

    float* wcatL[3] = {wcat, wcat + 128 * 256, wcat + 2 * 128 * 256};
    const int NSCAN = NN + 1;
    const int NB = (NSCAN + 255) / 256;

    // #1 pack weights + zero bn
    pack_all_kernel<<<(128 * 832 + 512 + 255) / 256, 256>>>(Wc[0], Wl[0], Wc[1], Wl[1],
                                                            Wc[2], Wl[2], wcat, bn);
    // #2-#3 CSR histogram
    zero_int_kernel<<<(NSCAN + 255) / 256, 256>>>(rowptr, NSCAN);
    hist_kernel<<<(EE + 255) / 256, 256>>>(dst, rowptr);
    // #4 GEMM layer 0  (positioned here so ncu's capture lands on it)
    {
        dim3 ggrid((NN + 127) / 128, 2);
        sgemm2_kernel<false><<<ggrid, 256>>>(feat, wcatL[0], z, lin, NN, 256, 128,
                                             nullptr, nullptr, nullptr);
    }
    // #5 attention logits layer 0
    eler_kernel<<<(NN * 4 + 255) / 256, 256>>>(z, al[0], ar[0], el, er, 32);
    // #6-#10 finish CSR build
    scan_block_kernel<<<NB, 256>>>(rowptr, NSCAN, bsum);
    scan_bsum_kernel<<<1, 256>>>(bsum, NB);
    scan_add_kernel<<<NB, 256>>>(rowptr, NSCAN, bsum);
    copy_int_kernel<<<(NN + 255) / 256, 256>>>(fill, rowptr, NN);
    scatter_kernel<<<(EE + 255) / 256, 256>>>(src, dst, fill, csrc);
    // #11-#12 agg + bn-stats layer 0
    agg_kernel<32, false><<<(NN + 7) / 8, 256>>>(rowptr, csrc, z, el, er, lin,
                                                 bc[0], nullptr, hbuf);
    bn_stats_kernel<<<256, 128>>>(hbuf, bn);
    // layer 1 (BN+ReLU fused into GEMM A-load)
    {
        dim3 ggrid((NN + 127) / 128, 2);
        sgemm2_kernel<true><<<ggrid, 256>>>(hbuf, wcatL[1], z, lin, NN, 256, 128,
                                            bn, gg[0], bb[0]);
    }
    eler_kernel<<<(NN * 4 + 255) / 256, 256>>>(z, al[1], ar[1], el, er, 32);
    agg_kernel<32, false><<<(NN + 7) / 8, 256>>>(rowptr, csrc, z, el, er, lin,
                                                 bc[1], nullptr, hbuf);
    bn_stats_kernel<<<256, 128>>>(hbuf, bn + 256);
    // layer 2 (BN+ReLU fused; head-mean epilogue)
    {
        dim3 ggrid((NN + 127) / 128, 3);
        sgemm2_kernel<true><<<ggrid, 256>>>(hbuf, wcatL[2], z, lin, NN, 320, 160,
                                            bn + 256, gg[1], bb[1]);
    }
    eler_kernel<<<(NN * 4 + 255) / 256, 256>>>(z, al[2], ar[2], el, er, 40);
    agg_kernel<40, true><<<(NN + 7) / 8, 256>>>(rowptr, csrc, z, el, er, lin,
                                                bc[2], bias_last, out);
}

// round 9
// speedup vs baseline: 1.1920x; 1.0886x over previous
#include <cuda_runtime.h>
#include <math.h>
#include <stdint.h>

#define NN 50000
#define EE 800000

// ---------------- scratch (static device globals; no allocation) ----------------
__device__ float g_z[NN * 160];
__device__ float g_lin[NN * 160];
__device__ float g_h[NN * 128];
__device__ float g_el[NN * 4];
__device__ float g_er[NN * 4];
__device__ float g_bn[512];              // layer0: [0,256), layer1: [256,512)
__device__ float g_wcat[128 * 832];      // packed [Wc0|Wl0][Wc1|Wl1][Wc2|Wl2]
__device__ int   g_rowptr[NN + 1];
__device__ int   g_fill[NN];
__device__ int   g_csrc[EE];
__device__ int   g_bsum[256];

// ---------------- small utils ----------------
__global__ void zero_int_kernel(int* p, int n) {
    int i = blockIdx.x * blockDim.x + threadIdx.x;
    if (i < n) p[i] = 0;
}

__global__ void hist_kernel(const int* __restrict__ dst, int* __restrict__ rowptr) {
    int e = blockIdx.x * blockDim.x + threadIdx.x;
    if (e < EE) atomicAdd(&rowptr[dst[e] + 1], 1);
}

// ---------------- decoupled 3-phase scan ----------------
__global__ void scan_block_kernel(int* __restrict__ data, int n, int* __restrict__ bsum) {
    __shared__ int wsum[8];
    int tid = threadIdx.x;
    int lane = tid & 31, wid = tid >> 5;
    int i = blockIdx.x * 256 + tid;
    int v = (i < n) ? data[i] : 0;
#pragma unroll
    for (int off = 1; off < 32; off <<= 1) {
        int t = __shfl_up_sync(0xffffffffu, v, off);
        if (lane >= off) v += t;
    }
    if (lane == 31) wsum[wid] = v;
    __syncthreads();
    if (wid == 0) {
        int w = (lane < 8) ? wsum[lane] : 0;
#pragma unroll
        for (int off = 1; off < 8; off <<= 1) {
            int t = __shfl_up_sync(0xffffffffu, w, off);
            if (lane >= off) w += t;
        }
        if (lane < 8) wsum[lane] = w;
    }
    __syncthreads();
    int add = (wid > 0) ? wsum[wid - 1] : 0;
    if (i < n) data[i] = v + add;
    if (tid == 255) bsum[blockIdx.x] = v + add;
}

__global__ void scan_bsum_kernel(int* __restrict__ bsum, int nb) {
    __shared__ int wsum[8];
    int tid = threadIdx.x;
    int lane = tid & 31, wid = tid >> 5;
    int v = (tid < nb) ? bsum[tid] : 0;
#pragma unroll
    for (int off = 1; off < 32; off <<= 1) {
        int t = __shfl_up_sync(0xffffffffu, v, off);
        if (lane >= off) v += t;
    }
    if (lane == 31) wsum[wid] = v;
    __syncthreads();
    if (wid == 0) {
        int w = (lane < 8) ? wsum[lane] : 0;
#pragma unroll
        for (int off = 1; off < 8; off <<= 1) {
            int t = __shfl_up_sync(0xffffffffu, w, off);
            if (lane >= off) w += t;
        }
        if (lane < 8) wsum[lane] = w;
    }
    __syncthreads();
    int add = (wid > 0) ? wsum[wid - 1] : 0;
    if (tid < nb) bsum[tid] = v + add;
}

__global__ void scan_add_kernel(int* __restrict__ data, int n, const int* __restrict__ bsum) {
    int i = blockIdx.x * 256 + threadIdx.x;
    if (blockIdx.x > 0 && i < n) data[i] += bsum[blockIdx.x - 1];
}

__global__ void copy_int_kernel(int* __restrict__ d, const int* __restrict__ s, int n) {
    int i = blockIdx.x * blockDim.x + threadIdx.x;
    if (i < n) d[i] = s[i];
}

__global__ void scatter_kernel(const int* __restrict__ src, const int* __restrict__ dst,
                               int* __restrict__ fill, int* __restrict__ csrc) {
    int e = blockIdx.x * blockDim.x + threadIdx.x;
    if (e < EE) {
        int pos = atomicAdd(&fill[dst[e]], 1);
        csrc[pos] = src[e];
    }
}

// ---------------- pack all weights once + zero BN buffers ----------------
__global__ void pack_all_kernel(const float* __restrict__ Wc0, const float* __restrict__ Wl0,
                                const float* __restrict__ Wc1, const float* __restrict__ Wl1,
                                const float* __restrict__ Wc2, const float* __restrict__ Wl2,
                                float* __restrict__ wcat, float* __restrict__ bn) {
    int idx = blockIdx.x * blockDim.x + threadIdx.x;
    if (idx < 512) { bn[idx] = 0.f; }
    int id = idx - 512;
    if (id < 0 || id >= 128 * 832) return;
    if (id < 32768) {
        int k = id >> 8, j = id & 255;
        wcat[id] = (j < 128) ? Wc0[k * 128 + j] : Wl0[k * 128 + (j - 128)];
    } else if (id < 65536) {
        int id2 = id - 32768;
        int k = id2 >> 8, j = id2 & 255;
        wcat[id] = (j < 128) ? Wc1[k * 128 + j] : Wl1[k * 128 + (j - 128)];
    } else {
        int id3 = id - 65536;
        int k = id3 / 320, j = id3 - k * 320;
        wcat[id] = (j < 160) ? Wc2[k * 160 + j] : Wl2[k * 160 + (j - 160)];
    }
}

// ---------------- SGEMM 128x128 tile, f32x2, 2-stage pipeline, K=128 --------
// C[N, Mtot] = act(A)[N,128] @ Wcat[128, Mtot]; epilogue splits cols Z / Lin.
// APPLY_BN: A element = relu(raw*scale[f] + shift[f]).
// ELER (Mh==128 only): blocks with blockIdx.y==0 hold full z rows; compute
// el/er = sum_c z[n,c]*al[c] / *ar[c] in the epilogue (flat al index == col).
__device__ __forceinline__ void fma_x2(unsigned long long& d, unsigned long long a,
                                       unsigned long long b) {
    asm("fma.rn.f32x2 %0, %1, %2, %0;" : "+l"(d) : "l"(a), "l"(b));
}

__device__ __forceinline__ unsigned long long dup_f32(float a) {
    unsigned long long r;
    asm("mov.b64 %0, {%1, %1};" : "=l"(r) : "r"(__float_as_uint(a)));
    return r;
}

template <bool APPLY_BN, bool ELER>
__global__ __launch_bounds__(256, 2)
void sgemm2_kernel(const float* __restrict__ A, const float* __restrict__ W,
                   float* __restrict__ Z, float* __restrict__ Lin,
                   int Nrows, int Mtot, int Mh,
                   const float* __restrict__ sums, const float* __restrict__ gamma,
                   const float* __restrict__ beta,
                   const float* __restrict__ al, const float* __restrict__ ar,
                   float* __restrict__ el, float* __restrict__ er) {
    __shared__ float As[2][16][132];
    __shared__ float Ws[2][16][128];
    __shared__ float scale_s[128], shift_s[128];
    int tid = threadIdx.x;
    int tx = tid & 15, ty = tid >> 4;
    int rowBase = blockIdx.x * 128;
    int colBase = blockIdx.y * 128;

    if (APPLY_BN) {
        if (tid < 128) {
            const float invN = 1.f / (float)NN;
            float mu = sums[tid] * invN;
            float var = fmaf(-mu, mu, sums[128 + tid] * invN);
            float s = gamma[tid] * rsqrtf(var + 1e-5f);
            scale_s[tid] = s;
            shift_s[tid] = fmaf(-mu, s, beta[tid]);
        }
        __syncthreads();
    }

    // load/store index precompute
    const int aR = tid >> 2;            // 0..63
    const int aV = (tid & 3) * 4;       // col-in-tile group {0,4,8,12}
    const int wR = tid >> 5;            // 0..7
    const int wC = (tid & 31) << 2;     // 0..124

    float4 ra0, ra1, rw0, rw1;

    auto ldg_tile = [&](int k0) {
        int gr0 = rowBase + aR;
        int gr1 = rowBase + aR + 64;
        ra0 = make_float4(0.f, 0.f, 0.f, 0.f);
        ra1 = make_float4(0.f, 0.f, 0.f, 0.f);
        if (gr0 < Nrows) ra0 = *reinterpret_cast<const float4*>(&A[(size_t)gr0 * 128 + k0 + aV]);
        if (gr1 < Nrows) ra1 = *reinterpret_cast<const float4*>(&A[(size_t)gr1 * 128 + k0 + aV]);
        int gc = colBase + wC;
        rw0 = make_float4(0.f, 0.f, 0.f, 0.f);
        rw1 = make_float4(0.f, 0.f, 0.f, 0.f);
        if (gc < Mtot) {
            rw0 = *reinterpret_cast<const float4*>(&W[(size_t)(k0 + wR) * Mtot + gc]);
            rw1 = *reinterpret_cast<const float4*>(&W[(size_t)(k0 + wR + 8) * Mtot + gc]);
        }
    };

    auto sts_tile = [&](int b, int k0) {
        float4 a0 = ra0, a1 = ra1;
        if (APPLY_BN) {
            int f = k0 + aV;
            float sc0 = scale_s[f + 0], sc1 = scale_s[f + 1];
            float sc2 = scale_s[f + 2], sc3 = scale_s[f + 3];
            float sh0 = shift_s[f + 0], sh1 = shift_s[f + 1];
            float sh2 = shift_s[f + 2], sh3 = shift_s[f + 3];
            a0.x = fmaxf(fmaf(a0.x, sc0, sh0), 0.f);
            a0.y = fmaxf(fmaf(a0.y, sc1, sh1), 0.f);
            a0.z = fmaxf(fmaf(a0.z, sc2, sh2), 0.f);
            a0.w = fmaxf(fmaf(a0.w, sc3, sh3), 0.f);
            a1.x = fmaxf(fmaf(a1.x, sc0, sh0), 0.f);
            a1.y = fmaxf(fmaf(a1.y, sc1, sh1), 0.f);
            a1.z = fmaxf(fmaf(a1.z, sc2, sh2), 0.f);
            a1.w = fmaxf(fmaf(a1.w, sc3, sh3), 0.f);
        }
        As[b][aV + 0][aR] = a0.x;      As[b][aV + 0][aR + 64] = a1.x;
        As[b][aV + 1][aR] = a0.y;      As[b][aV + 1][aR + 64] = a1.y;
        As[b][aV + 2][aR] = a0.z;      As[b][aV + 2][aR + 64] = a1.z;
        As[b][aV + 3][aR] = a0.w;      As[b][aV + 3][aR + 64] = a1.w;
        *reinterpret_cast<float4*>(&Ws[b][wR][wC]) = rw0;
        *reinterpret_cast<float4*>(&Ws[b][wR + 8][wC]) = rw1;
    };

    unsigned long long acc[8][4];
#pragma unroll
    for (int i = 0; i < 8; i++)
#pragma unroll
        for (int j = 0; j < 4; j++) acc[i][j] = 0ULL;

    // pipeline prologue: tile0 -> smem[0], tile1 -> regs
    ldg_tile(0);
    sts_tile(0, 0);
    ldg_tile(16);
    __syncthreads();

#pragma unroll
    for (int t = 0; t < 8; t++) {
        int buf = t & 1;
        if (t + 1 < 8) sts_tile(buf ^ 1, (t + 1) * 16);
        if (t + 2 < 8) ldg_tile((t + 2) * 16);
#pragma unroll
        for (int k = 0; k < 16; k++) {
            float4 a0 = *reinterpret_cast<const float4*>(&As[buf][k][ty * 8]);
            float4 a1 = *reinterpret_cast<const float4*>(&As[buf][k][ty * 8 + 4]);
            const unsigned long long* wp =
                reinterpret_cast<const unsigned long long*>(&Ws[buf][k][tx * 8]);
            unsigned long long w0 = wp[0], w1 = wp[1], w2 = wp[2], w3 = wp[3];
            float av[8] = {a0.x, a0.y, a0.z, a0.w, a1.x, a1.y, a1.z, a1.w};
#pragma unroll
            for (int i = 0; i < 8; i++) {
                unsigned long long ap = dup_f32(av[i]);
                fma_x2(acc[i][0], ap, w0);
                fma_x2(acc[i][1], ap, w1);
                fma_x2(acc[i][2], ap, w2);
                fma_x2(acc[i][3], ap, w3);
            }
        }
        __syncthreads();
    }

#pragma unroll
    for (int i = 0; i < 8; i++) {
        int r = rowBase + ty * 8 + i;
        if (r >= Nrows) continue;
#pragma unroll
        for (int j = 0; j < 4; j++) {
            int c = colBase + tx * 8 + j * 2;
            if (c >= Mtot) continue;
            float2 v = *reinterpret_cast<float2*>(&acc[i][j]);
            if (c < Mh)
                *reinterpret_cast<float2*>(&Z[(size_t)r * Mh + c]) = v;
            else
                *reinterpret_cast<float2*>(&Lin[(size_t)r * Mh + (c - Mh)]) = v;
        }
    }

    // fused attention-logit epilogue (Mh==128; z fully held by by==0 blocks)
    if (ELER && blockIdx.y == 0) {
        int c0 = tx * 8;
        float4 alA = *reinterpret_cast<const float4*>(&al[c0]);
        float4 alB = *reinterpret_cast<const float4*>(&al[c0 + 4]);
        float4 arA = *reinterpret_cast<const float4*>(&ar[c0]);
        float4 arB = *reinterpret_cast<const float4*>(&ar[c0 + 4]);
        float alv[8] = {alA.x, alA.y, alA.z, alA.w, alB.x, alB.y, alB.z, alB.w};
        float arv[8] = {arA.x, arA.y, arA.z, arA.w, arB.x, arB.y, arB.z, arB.w};
#pragma unroll
        for (int i = 0; i < 8; i++) {
            float pel = 0.f, per = 0.f;
#pragma unroll
            for (int j = 0; j < 4; j++) {
                float2 v = *reinterpret_cast<float2*>(&acc[i][j]);
                pel = fmaf(v.x, alv[j * 2], pel);
                pel = fmaf(v.y, alv[j * 2 + 1], pel);
                per = fmaf(v.x, arv[j * 2], per);
                per = fmaf(v.y, arv[j * 2 + 1], per);
            }
            pel += __shfl_xor_sync(0xffffffffu, pel, 1);
            pel += __shfl_xor_sync(0xffffffffu, pel, 2);
            per += __shfl_xor_sync(0xffffffffu, per, 1);
            per += __shfl_xor_sync(0xffffffffu, per, 2);
            if ((tx & 3) == 0) {
                int r = rowBase + ty * 8 + i;
                if (r < Nrows) {
                    int h = tx >> 2;
                    el[r * 4 + h] = pel;
                    er[r * 4 + h] = per;
                }
            }
        }
    }
}

// ---------------- el/er standalone (layer 2 only, Dh=40) ----------------
__global__ void eler_kernel(const float* __restrict__ z, const float* __restrict__ al,
                            const float* __restrict__ ar, float* __restrict__ el,
                            float* __restrict__ er, int Dh) {
    int idx = blockIdx.x * blockDim.x + threadIdx.x;
    if (idx >= NN * 4) return;
    int n = idx >> 2, h = idx & 3;
    const float* zp = z + (size_t)n * 4 * Dh + h * Dh;
    const float* alp = al + h * Dh;
    const float* arp = ar + h * Dh;
    float a = 0.f, b = 0.f;
    for (int d = 0; d < Dh; d++) {
        float v = zp[d];
        a = fmaf(v, alp[d], a);
        b = fmaf(v, arp[d], b);
    }
    el[idx] = a;
    er[idx] = b;
}

// ---------------- fused edge-softmax + aggregation (warp per dst node) -------
template <int Dh, bool MEAN>
__global__ void agg_kernel(const int* __restrict__ rowptr, const int* __restrict__ csrc,
                           const float* __restrict__ z, const float* __restrict__ el,
                           const float* __restrict__ er, const float* __restrict__ lin,
                           const float* __restrict__ bc, const float* __restrict__ bias_last,
                           float* __restrict__ out) {
    constexpr int F = 4 * Dh;
    constexpr bool EXTRA = (F == 160);
    __shared__ float sh[8][MEAN ? F : 1];
    int lane = threadIdx.x & 31;
    int w = threadIdx.x >> 5;
    int node = blockIdx.x * 8 + w;
    if (node >= NN) return;
    int beg = rowptr[node], end = rowptr[node + 1];

    float4 er4 = *reinterpret_cast<const float4*>(er + (size_t)node * 4);

    float m0 = -INFINITY, m1 = -INFINITY, m2 = -INFINITY, m3 = -INFINITY;
    for (int j = beg + lane; j < end; j += 32) {
        int s = csrc[j];
        float4 e4 = *reinterpret_cast<const float4*>(el + (size_t)s * 4);
        float e;
        e = e4.x + er4.x; e = e > 0.f ? e : 0.2f * e; m0 = fmaxf(m0, e);
        e = e4.y + er4.y; e = e > 0.f ? e : 0.2f * e; m1 = fmaxf(m1, e);
        e = e4.z + er4.z; e = e > 0.f ? e : 0.2f * e; m2 = fmaxf(m2, e);
        e = e4.w + er4.w; e = e > 0.f ? e : 0.2f * e; m3 = fmaxf(m3, e);
    }
#pragma unroll
    for (int off = 16; off; off >>= 1) {
        m0 = fmaxf(m0, __shfl_xor_sync(0xffffffffu, m0, off));
        m1 = fmaxf(m1, __shfl_xor_sync(0xffffffffu, m1, off));
        m2 = fmaxf(m2, __shfl_xor_sync(0xffffffffu, m2, off));
        m3 = fmaxf(m3, __shfl_xor_sync(0xffffffffu, m3, off));
    }

    const int h0 = (lane * 4) / Dh;

    float4 acc0 = make_float4(0.f, 0.f, 0.f, 0.f);
    float4 acc1 = make_float4(0.f, 0.f, 0.f, 0.f);
    float s0 = 0.f, s1 = 0.f, s2 = 0.f, s3 = 0.f;

    for (int j = beg; j < end; j++) {
        int sidx = csrc[j];
        float4 e4 = *reinterpret_cast<const float4*>(el + (size_t)sidx * 4);
        float e, x0, x1, x2, x3;
        e = e4.x + er4.x; e = e > 0.f ? e : 0.2f * e; x0 = __expf(e - m0); s0 += x0;
        e = e4.y + er4.y; e = e > 0.f ? e : 0.2f * e; x1 = __expf(e - m1); s1 += x1;
        e = e4.z + er4.z; e = e > 0.f ? e : 0.2f * e; x2 = __expf(e - m2); s2 += x2;
        e = e4.w + er4.w; e = e > 0.f ? e : 0.2f * e; x3 = __expf(e - m3); s3 += x3;
        const float4* zp = reinterpret_cast<const float4*>(z + (size_t)sidx * F);
        float4 zv = zp[lane];
        float xv = h0 == 0 ? x0 : h0 == 1 ? x1 : h0 == 2 ? x2 : x3;
        acc0.x = fmaf(xv, zv.x, acc0.x);
        acc0.y = fmaf(xv, zv.y, acc0.y);
        acc0.z = fmaf(xv, zv.z, acc0.z);
        acc0.w = fmaf(xv, zv.w, acc0.w);
        if (EXTRA && lane < 8) {
            float4 zv1 = zp[32 + lane];
            acc1.x = fmaf(x3, zv1.x, acc1.x);
            acc1.y = fmaf(x3, zv1.y, acc1.y);
            acc1.z = fmaf(x3, zv1.z, acc1.z);
            acc1.w = fmaf(x3, zv1.w, acc1.w);
        }
    }

    float i0 = s0 > 0.f ? 1.f / s0 : 1.f;
    float i1 = s1 > 0.f ? 1.f / s1 : 1.f;
    float i2 = s2 > 0.f ? 1.f / s2 : 1.f;
    float i3 = s3 > 0.f ? 1.f / s3 : 1.f;
    float iv0 = h0 == 0 ? i0 : h0 == 1 ? i1 : h0 == 2 ? i2 : i3;

    int f = lane * 4;
    if (!MEAN) {
        float4 l4 = *reinterpret_cast<const float4*>(lin + (size_t)node * F + f);
        float4 b4 = *reinterpret_cast<const float4*>(bc + f);
        float4 r;
        r.x = fmaf(acc0.x, iv0, b4.x + l4.x);
        r.y = fmaf(acc0.y, iv0, b4.y + l4.y);
        r.z = fmaf(acc0.z, iv0, b4.z + l4.z);
        r.w = fmaf(acc0.w, iv0, b4.w + l4.w);
        *reinterpret_cast<float4*>(out + (size_t)node * F + f) = r;
    } else {
        float4 l4 = *reinterpret_cast<const float4*>(lin + (size_t)node * F + f);
        float4 b4 = *reinterpret_cast<const float4*>(bc + f);
        sh[w][f + 0] = fmaf(acc0.x, iv0, b4.x + l4.x);
        sh[w][f + 1] = fmaf(acc0.y, iv0, b4.y + l4.y);
        sh[w][f + 2] = fmaf(acc0.z, iv0, b4.z + l4.z);
        sh[w][f + 3] = fmaf(acc0.w, iv0, b4.w + l4.w);
        if (EXTRA && lane < 8) {
            int f1 = 128 + lane * 4;
            float4 l41 = *reinterpret_cast<const float4*>(lin + (size_t)node * F + f1);
            float4 b41 = *reinterpret_cast<const float4*>(bc + f1);
            sh[w][f1 + 0] = fmaf(acc1.x, i3, b41.x + l41.x);
            sh[w][f1 + 1] = fmaf(acc1.y, i3, b41.y + l41.y);
            sh[w][f1 + 2] = fmaf(acc1.z, i3, b41.z + l41.z);
            sh[w][f1 + 3] = fmaf(acc1.w, i3, b41.w + l41.w);
        }
        __syncwarp();
        for (int cc = lane; cc < Dh; cc += 32) {
            float v = sh[w][cc] + sh[w][Dh + cc] + sh[w][2 * Dh + cc] + sh[w][3 * Dh + cc];
            out[(size_t)node * Dh + cc] = fmaf(v, 0.25f, bias_last[cc]);
        }
    }
}

// ---------------- BatchNorm stats (sum / sumsq per feature, F=128) ----------
__global__ void bn_stats_kernel(const float* __restrict__ x, float* __restrict__ sums) {
    int f = threadIdx.x;  // 128 threads
    float s = 0.f, s2 = 0.f;
    for (int n = blockIdx.x; n < NN; n += gridDim.x) {
        float v = x[(size_t)n * 128 + f];
        s += v;
        s2 = fmaf(v, v, s2);
    }
    atomicAdd(&sums[f], s);
    atomicAdd(&sums[128 + f], s2);
}

// ---------------- host orchestration ----------------
extern "C" void kernel_launch(void* const* d_in, const int* in_sizes, int n_in,
                              void* d_out, int out_size) {
    (void)in_sizes; (void)n_in; (void)out_size;
    const float* feat = (const float*)d_in[0];
    const int* src = (const int*)d_in[1];
    const int* dst = (const int*)d_in[2];
    const float* Wc[3] = {(const float*)d_in[3], (const float*)d_in[8], (const float*)d_in[13]};
    const float* al[3] = {(const float*)d_in[4], (const float*)d_in[9], (const float*)d_in[14]};
    const float* ar[3] = {(const float*)d_in[5], (const float*)d_in[10], (const float*)d_in[15]};
    const float* bc[3] = {(const float*)d_in[6], (const float*)d_in[11], (const float*)d_in[16]};
    const float* Wl[3] = {(const float*)d_in[7], (const float*)d_in[12], (const float*)d_in[17]};
    const float* gg[2] = {(const float*)d_in[18], (const float*)d_in[20]};
    const float* bb[2] = {(const float*)d_in[19], (const float*)d_in[21]};
    const float* bias_last = (const float*)d_in[22];
    float* out = (float*)d_out;

    void* p;
    cudaGetSymbolAddress(&p, g_z);      float* z = (float*)p;
    cudaGetSymbolAddress(&p, g_lin);    float* lin = (float*)p;
    cudaGetSymbolAddress(&p, g_h);      float* hbuf = (float*)p;
    cudaGetSymbolAddress(&p, g_el);     float* el = (float*)p;
    cudaGetSymbolAddress(&p, g_er);     float* er = (float*)p;
    cudaGetSymbolAddress(&p, g_bn);     float* bn = (float*)p;
    cudaGetSymbolAddress(&p, g_wcat);   float* wcat = (float*)p;
    cudaGetSymbolAddress(&p, g_rowptr); int* rowptr = (int*)p;
    cudaGetSymbolAddress(&p, g_fill);   int* fill = (int*)p;
    cudaGetSymbolAddress(&p, g_csrc);   int* csrc = (int*)p;
    cudaGetSymbolAddress(&p, g_bsum);   int* bsum = (int*)p;

    float* wcatL[3] = {wcat, wcat + 128 * 256, wcat + 2 * 128 * 256};
    const int NSCAN = NN + 1;
    const int NB = (NSCAN + 255) / 256;

    // #1 pack weights + zero bn
    pack_all_kernel<<<(128 * 832 + 512 + 255) / 256, 256>>>(Wc[0], Wl[0], Wc[1], Wl[1],
                                                            Wc[2], Wl[2], wcat, bn);
    // #2-#3 CSR histogram
    zero_int_kernel<<<(NSCAN + 255) / 256, 256>>>(rowptr, NSCAN);
    hist_kernel<<<(EE + 255) / 256, 256>>>(dst, rowptr);
    // #4 GEMM layer 0 (+fused el/er)  — positioned so ncu capture lands here
    {
        dim3 ggrid((NN + 127) / 128, 2);
        sgemm2_kernel<false, true><<<ggrid, 256>>>(feat, wcatL[0], z, lin, NN, 256, 128,
                                                   nullptr, nullptr, nullptr,
                                                   al[0], ar[0], el, er);
    }
    // #5-#9 finish CSR build
    scan_block_kernel<<<NB, 256>>>(rowptr, NSCAN, bsum);
    scan_bsum_kernel<<<1, 256>>>(bsum, NB);
    scan_add_kernel<<<NB, 256>>>(rowptr, NSCAN, bsum);
    copy_int_kernel<<<(NN + 255) / 256, 256>>>(fill, rowptr, NN);
    scatter_kernel<<<(EE + 255) / 256, 256>>>(src, dst, fill, csrc);
    // #10-#11 agg + bn-stats layer 0
    agg_kernel<32, false><<<(NN + 7) / 8, 256>>>(rowptr, csrc, z, el, er, lin,
                                                 bc[0], nullptr, hbuf);
    bn_stats_kernel<<<256, 128>>>(hbuf, bn);
    // layer 1 (BN+ReLU fused into GEMM A-load; el/er fused into epilogue)
    {
        dim3 ggrid((NN + 127) / 128, 2);
        sgemm2_kernel<true, true><<<ggrid, 256>>>(hbuf, wcatL[1], z, lin, NN, 256, 128,
                                                  bn, gg[0], bb[0], al[1], ar[1], el, er);
    }
    agg_kernel<32, false><<<(NN + 7) / 8, 256>>>(rowptr, csrc, z, el, er, lin,
                                                 bc[1], nullptr, hbuf);
    bn_stats_kernel<<<256, 128>>>(hbuf, bn + 256);
    // layer 2 (BN+ReLU fused; Mh=160 -> standalone eler; head-mean epilogue)
    {
        dim3 ggrid((NN + 127) / 128, 3);
        sgemm2_kernel<true, false><<<ggrid, 256>>>(hbuf, wcatL[2], z, lin, NN, 320, 160,
                                                   bn + 256, gg[1], bb[1],
                                                   nullptr, nullptr, nullptr, nullptr);
    }
    eler_kernel<<<(NN * 4 + 255) / 256, 256>>>(z, al[2], ar[2], el, er, 40);
    agg_kernel<40, true><<<(NN + 7) / 8, 256>>>(rowptr, csrc, z, el, er, lin,
                                                bc[2], bias_last, out);
}

// round 17
// speedup vs baseline: 1.6106x; 1.3512x over previous
#include <cuda_runtime.h>
#include <math.h>
#include <stdint.h>

#define NN 50000
#define EE 800000

// ---------------- scratch (static device globals; no allocation) ----------------
__device__ float g_z[NN * 160];
__device__ float g_lin[NN * 160];
__device__ float g_h[NN * 128];
__device__ float g_el[NN * 4];
__device__ float g_er[NN * 4];
__device__ float g_bn[512];              // layer0: [0,256), layer1: [256,512)
__device__ float g_wcat[128 * 832];      // packed [Wc0|Wl0][Wc1|Wl1][Wc2|Wl2]
__device__ int   g_rowptr[NN + 1];
__device__ int   g_fill[NN];
__device__ int   g_csrc[EE];
__device__ int   g_bsum[256];

// ---------------- small utils ----------------
__global__ void zero_int_kernel(int* p, int n) {
    int i = blockIdx.x * blockDim.x + threadIdx.x;
    if (i < n) p[i] = 0;
}

__global__ void hist_kernel(const int* __restrict__ dst, int* __restrict__ rowptr) {
    int e = blockIdx.x * blockDim.x + threadIdx.x;
    if (e < EE) atomicAdd(&rowptr[dst[e] + 1], 1);
}

// ---------------- decoupled 3-phase scan ----------------
__global__ void scan_block_kernel(int* __restrict__ data, int n, int* __restrict__ bsum) {
    __shared__ int wsum[8];
    int tid = threadIdx.x, lane = tid & 31, wid = tid >> 5;
    int i = blockIdx.x * 256 + tid;
    int v = (i < n) ? data[i] : 0;
#pragma unroll
    for (int off = 1; off < 32; off <<= 1) {
        int t = __shfl_up_sync(0xffffffffu, v, off);
        if (lane >= off) v += t;
    }
    if (lane == 31) wsum[wid] = v;
    __syncthreads();
    if (wid == 0) {
        int w = (lane < 8) ? wsum[lane] : 0;
#pragma unroll
        for (int off = 1; off < 8; off <<= 1) {
            int t = __shfl_up_sync(0xffffffffu, w, off);
            if (lane >= off) w += t;
        }
        if (lane < 8) wsum[lane] = w;
    }
    __syncthreads();
    int add = (wid > 0) ? wsum[wid - 1] : 0;
    if (i < n) data[i] = v + add;
    if (tid == 255) bsum[blockIdx.x] = v + add;
}

__global__ void scan_bsum_kernel(int* __restrict__ bsum, int nb) {
    __shared__ int wsum[8];
    int tid = threadIdx.x, lane = tid & 31, wid = tid >> 5;
    int v = (tid < nb) ? bsum[tid] : 0;
#pragma unroll
    for (int off = 1; off < 32; off <<= 1) {
        int t = __shfl_up_sync(0xffffffffu, v, off);
        if (lane >= off) v += t;
    }
    if (lane == 31) wsum[wid] = v;
    __syncthreads();
    if (wid == 0) {
        int w = (lane < 8) ? wsum[lane] : 0;
#pragma unroll
        for (int off = 1; off < 8; off <<= 1) {
            int t = __shfl_up_sync(0xffffffffu, w, off);
            if (lane >= off) w += t;
        }
        if (lane < 8) wsum[lane] = w;
    }
    __syncthreads();
    int add = (wid > 0) ? wsum[wid - 1] : 0;
    if (tid < nb) bsum[tid] = v + add;
}

// phase 3: add block offsets AND emit fill[] copy (merged kernel)
__global__ void scan_add_fill_kernel(int* __restrict__ data, int n,
                                     const int* __restrict__ bsum, int* __restrict__ fill) {
    int i = blockIdx.x * 256 + threadIdx.x;
    if (i >= n) return;
    int add = (blockIdx.x > 0) ? bsum[blockIdx.x - 1] : 0;
    int v = data[i] + add;
    data[i] = v;
    if (i < NN) fill[i] = v;
}

__global__ void scatter_kernel(const int* __restrict__ src, const int* __restrict__ dst,
                               int* __restrict__ fill, int* __restrict__ csrc) {
    int e = blockIdx.x * blockDim.x + threadIdx.x;
    if (e < EE) {
        int pos = atomicAdd(&fill[dst[e]], 1);
        csrc[pos] = src[e];
    }
}

// ---------------- pack all weights once + zero BN buffers ----------------
__global__ void pack_all_kernel(const float* __restrict__ Wc0, const float* __restrict__ Wl0,
                                const float* __restrict__ Wc1, const float* __restrict__ Wl1,
                                const float* __restrict__ Wc2, const float* __restrict__ Wl2,
                                float* __restrict__ wcat, float* __restrict__ bn) {
    int idx = blockIdx.x * blockDim.x + threadIdx.x;
    if (idx < 512) { bn[idx] = 0.f; }
    int id = idx - 512;
    if (id < 0 || id >= 128 * 832) return;
    if (id < 32768) {
        int k = id >> 8, j = id & 255;
        wcat[id] = (j < 128) ? Wc0[k * 128 + j] : Wl0[k * 128 + (j - 128)];
    } else if (id < 65536) {
        int id2 = id - 32768;
        int k = id2 >> 8, j = id2 & 255;
        wcat[id] = (j < 128) ? Wc1[k * 128 + j] : Wl1[k * 128 + (j - 128)];
    } else {
        int id3 = id - 65536;
        int k = id3 / 320, j = id3 - k * 320;
        wcat[id] = (j < 160) ? Wc2[k * 160 + j] : Wl2[k * 160 + (j - 160)];
    }
}

// ---------------- SGEMM 128x64 tile, f32x2, 2-stage pipeline, K=128 ---------
// 3 CTAs/SM target (8x4 accum keeps regs ~80). Epilogue splits Z/Lin.
// ELER (Mh==128, colBase<128): fused attention logits via 8-lane shuffles.
__device__ __forceinline__ void fma_x2(unsigned long long& d, unsigned long long a,
                                       unsigned long long b) {
    asm("fma.rn.f32x2 %0, %1, %2, %0;" : "+l"(d) : "l"(a), "l"(b));
}

__device__ __forceinline__ unsigned long long dup_f32(float a) {
    unsigned long long r;
    asm("mov.b64 %0, {%1, %1};" : "=l"(r) : "r"(__float_as_uint(a)));
    return r;
}

template <bool APPLY_BN, bool ELER>
__global__ __launch_bounds__(256, 3)
void sgemm2_kernel(const float* __restrict__ A, const float* __restrict__ W,
                   float* __restrict__ Z, float* __restrict__ Lin,
                   int Nrows, int Mtot, int Mh,
                   const float* __restrict__ sums, const float* __restrict__ gamma,
                   const float* __restrict__ beta,
                   const float* __restrict__ al, const float* __restrict__ ar,
                   float* __restrict__ el, float* __restrict__ er) {
    __shared__ float As[2][16][132];
    __shared__ float Ws[2][16][64];
    __shared__ float scale_s[128], shift_s[128];
    int tid = threadIdx.x;
    int tx = tid & 15, ty = tid >> 4;
    int rowBase = blockIdx.x * 128;
    int colBase = blockIdx.y * 64;

    if (APPLY_BN) {
        if (tid < 128) {
            const float invN = 1.f / (float)NN;
            float mu = sums[tid] * invN;
            float var = fmaf(-mu, mu, sums[128 + tid] * invN);
            float s = gamma[tid] * rsqrtf(var + 1e-5f);
            scale_s[tid] = s;
            shift_s[tid] = fmaf(-mu, s, beta[tid]);
        }
        __syncthreads();
    }

    const int aR = tid >> 2;            // 0..63
    const int aV = (tid & 3) * 4;       // {0,4,8,12}
    const int wR = tid >> 4;            // 0..15
    const int wC = (tid & 15) * 4;      // 0..60

    float4 ra0, ra1, rw0;

    auto ldg_tile = [&](int k0) {
        int gr0 = rowBase + aR;
        int gr1 = rowBase + aR + 64;
        ra0 = make_float4(0.f, 0.f, 0.f, 0.f);
        ra1 = make_float4(0.f, 0.f, 0.f, 0.f);
        if (gr0 < Nrows) ra0 = *reinterpret_cast<const float4*>(&A[(size_t)gr0 * 128 + k0 + aV]);
        if (gr1 < Nrows) ra1 = *reinterpret_cast<const float4*>(&A[(size_t)gr1 * 128 + k0 + aV]);
        rw0 = *reinterpret_cast<const float4*>(&W[(size_t)(k0 + wR) * Mtot + colBase + wC]);
    };

    auto sts_tile = [&](int b, int k0) {
        float4 a0 = ra0, a1 = ra1;
        if (APPLY_BN) {
            int f = k0 + aV;
            float sc0 = scale_s[f + 0], sc1 = scale_s[f + 1];
            float sc2 = scale_s[f + 2], sc3 = scale_s[f + 3];
            float sh0 = shift_s[f + 0], sh1 = shift_s[f + 1];
            float sh2 = shift_s[f + 2], sh3 = shift_s[f + 3];
            a0.x = fmaxf(fmaf(a0.x, sc0, sh0), 0.f);
            a0.y = fmaxf(fmaf(a0.y, sc1, sh1), 0.f);
            a0.z = fmaxf(fmaf(a0.z, sc2, sh2), 0.f);
            a0.w = fmaxf(fmaf(a0.w, sc3, sh3), 0.f);
            a1.x = fmaxf(fmaf(a1.x, sc0, sh0), 0.f);
            a1.y = fmaxf(fmaf(a1.y, sc1, sh1), 0.f);
            a1.z = fmaxf(fmaf(a1.z, sc2, sh2), 0.f);
            a1.w = fmaxf(fmaf(a1.w, sc3, sh3), 0.f);
        }
        As[b][aV + 0][aR] = a0.x;      As[b][aV + 0][aR + 64] = a1.x;
        As[b][aV + 1][aR] = a0.y;      As[b][aV + 1][aR + 64] = a1.y;
        As[b][aV + 2][aR] = a0.z;      As[b][aV + 2][aR + 64] = a1.z;
        As[b][aV + 3][aR] = a0.w;      As[b][aV + 3][aR + 64] = a1.w;
        *reinterpret_cast<float4*>(&Ws[b][wR][wC]) = rw0;
    };

    unsigned long long acc[8][2];
#pragma unroll
    for (int i = 0; i < 8; i++) { acc[i][0] = 0ULL; acc[i][1] = 0ULL; }

    ldg_tile(0);
    sts_tile(0, 0);
    ldg_tile(16);
    __syncthreads();

#pragma unroll
    for (int t = 0; t < 8; t++) {
        int buf = t & 1;
        if (t + 1 < 8) sts_tile(buf ^ 1, (t + 1) * 16);
        if (t + 2 < 8) ldg_tile((t + 2) * 16);
#pragma unroll
        for (int k = 0; k < 16; k++) {
            float4 a0 = *reinterpret_cast<const float4*>(&As[buf][k][ty * 8]);
            float4 a1 = *reinterpret_cast<const float4*>(&As[buf][k][ty * 8 + 4]);
            const unsigned long long* wp =
                reinterpret_cast<const unsigned long long*>(&Ws[buf][k][tx * 4]);
            unsigned long long w0 = wp[0], w1 = wp[1];
            float av[8] = {a0.x, a0.y, a0.z, a0.w, a1.x, a1.y, a1.z, a1.w};
#pragma unroll
            for (int i = 0; i < 8; i++) {
                unsigned long long ap = dup_f32(av[i]);
                fma_x2(acc[i][0], ap, w0);
                fma_x2(acc[i][1], ap, w1);
            }
        }
        __syncthreads();
    }

    int c0 = colBase + tx * 4;
#pragma unroll
    for (int i = 0; i < 8; i++) {
        int r = rowBase + ty * 8 + i;
        if (r >= Nrows) continue;
        float2 vA = *reinterpret_cast<float2*>(&acc[i][0]);
        float2 vB = *reinterpret_cast<float2*>(&acc[i][1]);
        float4 v = make_float4(vA.x, vA.y, vB.x, vB.y);
        if (c0 < Mh)
            *reinterpret_cast<float4*>(&Z[(size_t)r * Mh + c0]) = v;
        else
            *reinterpret_cast<float4*>(&Lin[(size_t)r * Mh + (c0 - Mh)]) = v;
    }

    // fused attention-logit epilogue (Mh==128; heads are 32-col groups)
    if (ELER && colBase < 128) {
        float4 alv = *reinterpret_cast<const float4*>(&al[c0]);
        float4 arv = *reinterpret_cast<const float4*>(&ar[c0]);
        int head = c0 >> 5;   // valid for lanes with (tx&7)==0
#pragma unroll
        for (int i = 0; i < 8; i++) {
            float2 vA = *reinterpret_cast<float2*>(&acc[i][0]);
            float2 vB = *reinterpret_cast<float2*>(&acc[i][1]);
            float pel = vA.x * alv.x;
            pel = fmaf(vA.y, alv.y, pel);
            pel = fmaf(vB.x, alv.z, pel);
            pel = fmaf(vB.y, alv.w, pel);
            float per = vA.x * arv.x;
            per = fmaf(vA.y, arv.y, per);
            per = fmaf(vB.x, arv.z, per);
            per = fmaf(vB.y, arv.w, per);
            pel += __shfl_xor_sync(0xffffffffu, pel, 1);
            pel += __shfl_xor_sync(0xffffffffu, pel, 2);
            pel += __shfl_xor_sync(0xffffffffu, pel, 4);
            per += __shfl_xor_sync(0xffffffffu, per, 1);
            per += __shfl_xor_sync(0xffffffffu, per, 2);
            per += __shfl_xor_sync(0xffffffffu, per, 4);
            if ((tx & 7) == 0) {
                int r = rowBase + ty * 8 + i;
                if (r < Nrows) {
                    el[r * 4 + head] = pel;
                    er[r * 4 + head] = per;
                }
            }
        }
    }
}

// ---------------- el/er standalone (layer 2, Dh=40), float4 loads ----------
__global__ void eler_kernel(const float* __restrict__ z, const float* __restrict__ al,
                            const float* __restrict__ ar, float* __restrict__ el,
                            float* __restrict__ er) {
    int idx = blockIdx.x * blockDim.x + threadIdx.x;
    if (idx >= NN * 4) return;
    int n = idx >> 2, h = idx & 3;
    const float* zp = z + (size_t)n * 160 + h * 40;
    const float* alp = al + h * 40;
    const float* arp = ar + h * 40;
    float a = 0.f, b = 0.f;
#pragma unroll
    for (int d = 0; d < 40; d += 4) {
        float4 v = *reinterpret_cast<const float4*>(zp + d);
        float4 A = *reinterpret_cast<const float4*>(alp + d);
        float4 B = *reinterpret_cast<const float4*>(arp + d);
        a = fmaf(v.x, A.x, a); a = fmaf(v.y, A.y, a);
        a = fmaf(v.z, A.z, a); a = fmaf(v.w, A.w, a);
        b = fmaf(v.x, B.x, b); b = fmaf(v.y, B.y, b);
        b = fmaf(v.z, B.z, b); b = fmaf(v.w, B.w, b);
    }
    el[idx] = a;
    er[idx] = b;
}

// ---------------- fused edge-softmax + aggregation (warp per dst node) -------
// STATS: additionally accumulate per-feature sum/sumsq of the output h into
// bnsums via block-level smem transpose + 2 atomicAdds per column.
// Grid is exactly NN/8 blocks (NN % 8 == 0), so no partial blocks.
template <int Dh, bool MEAN, bool STATS>
__global__ void agg_kernel(const int* __restrict__ rowptr, const int* __restrict__ csrc,
                           const float* __restrict__ z, const float* __restrict__ el,
                           const float* __restrict__ er, const float* __restrict__ lin,
                           const float* __restrict__ bc, const float* __restrict__ bias_last,
                           float* __restrict__ out, float* __restrict__ bnsums) {
    constexpr int F = 4 * Dh;
    constexpr bool EXTRA = (F == 160);
    __shared__ float sh[8][(MEAN || STATS) ? F : 1];
    int lane = threadIdx.x & 31;
    int w = threadIdx.x >> 5;
    int node = blockIdx.x * 8 + w;
    int beg = rowptr[node], end = rowptr[node + 1];

    float4 er4 = *reinterpret_cast<const float4*>(er + (size_t)node * 4);

    float m0 = -INFINITY, m1 = -INFINITY, m2 = -INFINITY, m3 = -INFINITY;
    for (int j = beg + lane; j < end; j += 32) {
        int s = csrc[j];
        float4 e4 = *reinterpret_cast<const float4*>(el + (size_t)s * 4);
        float e;
        e = e4.x + er4.x; e = e > 0.f ? e : 0.2f * e; m0 = fmaxf(m0, e);
        e = e4.y + er4.y; e = e > 0.f ? e : 0.2f * e; m1 = fmaxf(m1, e);
        e = e4.z + er4.z; e = e > 0.f ? e : 0.2f * e; m2 = fmaxf(m2, e);
        e = e4.w + er4.w; e = e > 0.f ? e : 0.2f * e; m3 = fmaxf(m3, e);
    }
#pragma unroll
    for (int off = 16; off; off >>= 1) {
        m0 = fmaxf(m0, __shfl_xor_sync(0xffffffffu, m0, off));
        m1 = fmaxf(m1, __shfl_xor_sync(0xffffffffu, m1, off));
        m2 = fmaxf(m2, __shfl_xor_sync(0xffffffffu, m2, off));
        m3 = fmaxf(m3, __shfl_xor_sync(0xffffffffu, m3, off));
    }

    const int h0 = (lane * 4) / Dh;

    float4 acc0 = make_float4(0.f, 0.f, 0.f, 0.f);
    float4 acc1 = make_float4(0.f, 0.f, 0.f, 0.f);
    float s0 = 0.f, s1 = 0.f, s2 = 0.f, s3 = 0.f;

    for (int j = beg; j < end; j++) {
        int sidx = csrc[j];
        float4 e4 = *reinterpret_cast<const float4*>(el + (size_t)sidx * 4);
        float e, x0, x1, x2, x3;
        e = e4.x + er4.x; e = e > 0.f ? e : 0.2f * e; x0 = __expf(e - m0); s0 += x0;
        e = e4.y + er4.y; e = e > 0.f ? e : 0.2f * e; x1 = __expf(e - m1); s1 += x1;
        e = e4.z + er4.z; e = e > 0.f ? e : 0.2f * e; x2 = __expf(e - m2); s2 += x2;
        e = e4.w + er4.w; e = e > 0.f ? e : 0.2f * e; x3 = __expf(e - m3); s3 += x3;
        const float4* zp = reinterpret_cast<const float4*>(z + (size_t)sidx * F);
        float4 zv = zp[lane];
        float xv = h0 == 0 ? x0 : h0 == 1 ? x1 : h0 == 2 ? x2 : x3;
        acc0.x = fmaf(xv, zv.x, acc0.x);
        acc0.y = fmaf(xv, zv.y, acc0.y);
        acc0.z = fmaf(xv, zv.z, acc0.z);
        acc0.w = fmaf(xv, zv.w, acc0.w);
        if (EXTRA && lane < 8) {
            float4 zv1 = zp[32 + lane];
            acc1.x = fmaf(x3, zv1.x, acc1.x);
            acc1.y = fmaf(x3, zv1.y, acc1.y);
            acc1.z = fmaf(x3, zv1.z, acc1.z);
            acc1.w = fmaf(x3, zv1.w, acc1.w);
        }
    }

    float i0 = s0 > 0.f ? 1.f / s0 : 1.f;
    float i1 = s1 > 0.f ? 1.f / s1 : 1.f;
    float i2 = s2 > 0.f ? 1.f / s2 : 1.f;
    float i3 = s3 > 0.f ? 1.f / s3 : 1.f;
    float iv0 = h0 == 0 ? i0 : h0 == 1 ? i1 : h0 == 2 ? i2 : i3;

    int f = lane * 4;
    if (!MEAN) {
        float4 l4 = *reinterpret_cast<const float4*>(lin + (size_t)node * F + f);
        float4 b4 = *reinterpret_cast<const float4*>(bc + f);
        float4 r;
        r.x = fmaf(acc0.x, iv0, b4.x + l4.x);
        r.y = fmaf(acc0.y, iv0, b4.y + l4.y);
        r.z = fmaf(acc0.z, iv0, b4.z + l4.z);
        r.w = fmaf(acc0.w, iv0, b4.w + l4.w);
        *reinterpret_cast<float4*>(out + (size_t)node * F + f) = r;
        if (STATS) {
            sh[w][f + 0] = r.x;
            sh[w][f + 1] = r.y;
            sh[w][f + 2] = r.z;
            sh[w][f + 3] = r.w;
        }
    } else {
        float4 l4 = *reinterpret_cast<const float4*>(lin + (size_t)node * F + f);
        float4 b4 = *reinterpret_cast<const float4*>(bc + f);
        sh[w][f + 0] = fmaf(acc0.x, iv0, b4.x + l4.x);
        sh[w][f + 1] = fmaf(acc0.y, iv0, b4.y + l4.y);
        sh[w][f + 2] = fmaf(acc0.z, iv0, b4.z + l4.z);
        sh[w][f + 3] = fmaf(acc0.w, iv0, b4.w + l4.w);
        if (EXTRA && lane < 8) {
            int f1 = 128 + lane * 4;
            float4 l41 = *reinterpret_cast<const float4*>(lin + (size_t)node * F + f1);
            float4 b41 = *reinterpret_cast<const float4*>(bc + f1);
            sh[w][f1 + 0] = fmaf(acc1.x, i3, b41.x + l41.x);
            sh[w][f1 + 1] = fmaf(acc1.y, i3, b41.y + l41.y);
            sh[w][f1 + 2] = fmaf(acc1.z, i3, b41.z + l41.z);
            sh[w][f1 + 3] = fmaf(acc1.w, i3, b41.w + l41.w);
        }
        __syncwarp();
        for (int cc = lane; cc < Dh; cc += 32) {
            float v = sh[w][cc] + sh[w][Dh + cc] + sh[w][2 * Dh + cc] + sh[w][3 * Dh + cc];
            out[(size_t)node * Dh + cc] = fmaf(v, 0.25f, bias_last[cc]);
        }
    }

    if (STATS) {
        __syncthreads();
        int c = threadIdx.x;
        if (c < F) {
            float s = 0.f, s2 = 0.f;
#pragma unroll
            for (int q = 0; q < 8; q++) {
                float v = sh[q][c];
                s += v;
                s2 = fmaf(v, v, s2);
            }
            atomicAdd(&bnsums[c], s);
            atomicAdd(&bnsums[F + c], s2);
        }
    }
}

// ---------------- host orchestration ----------------
extern "C" void kernel_launch(void* const* d_in, const int* in_sizes, int n_in,
                              void* d_out, int out_size) {
    (void)in_sizes; (void)n_in; (void)out_size;
    const float* feat = (const float*)d_in[0];
    const int* src = (const int*)d_in[1];
    const int* dst = (const int*)d_in[2];
    const float* Wc[3] = {(const float*)d_in[3], (const float*)d_in[8], (const float*)d_in[13]};
    const float* al[3] = {(const float*)d_in[4], (const float*)d_in[9], (const float*)d_in[14]};
    const float* ar[3] = {(const float*)d_in[5], (const float*)d_in[10], (const float*)d_in[15]};
    const float* bc[3] = {(const float*)d_in[6], (const float*)d_in[11], (const float*)d_in[16]};
    const float* Wl[3] = {(const float*)d_in[7], (const float*)d_in[12], (const float*)d_in[17]};
    const float* gg[2] = {(const float*)d_in[18], (const float*)d_in[20]};
    const float* bb[2] = {(const float*)d_in[19], (const float*)d_in[21]};
    const float* bias_last = (const float*)d_in[22];
    float* out = (float*)d_out;

    void* p;
    cudaGetSymbolAddress(&p, g_z);      float* z = (float*)p;
    cudaGetSymbolAddress(&p, g_lin);    float* lin = (float*)p;
    cudaGetSymbolAddress(&p, g_h);      float* hbuf = (float*)p;
    cudaGetSymbolAddress(&p, g_el);     float* el = (float*)p;
    cudaGetSymbolAddress(&p, g_er);     float* er = (float*)p;
    cudaGetSymbolAddress(&p, g_bn);     float* bn = (float*)p;
    cudaGetSymbolAddress(&p, g_wcat);   float* wcat = (float*)p;
    cudaGetSymbolAddress(&p, g_rowptr); int* rowptr = (int*)p;
    cudaGetSymbolAddress(&p, g_fill);   int* fill = (int*)p;
    cudaGetSymbolAddress(&p, g_csrc);   int* csrc = (int*)p;
    cudaGetSymbolAddress(&p, g_bsum);   int* bsum = (int*)p;

    float* wcatL[3] = {wcat, wcat + 128 * 256, wcat + 2 * 128 * 256};
    const int NSCAN = NN + 1;
    const int NB = (NSCAN + 255) / 256;

    // #1 pack weights + zero bn
    pack_all_kernel<<<(128 * 832 + 512 + 255) / 256, 256>>>(Wc[0], Wl[0], Wc[1], Wl[1],
                                                            Wc[2], Wl[2], wcat, bn);
    // #2-#3 CSR histogram
    zero_int_kernel<<<(NSCAN + 255) / 256, 256>>>(rowptr, NSCAN);
    hist_kernel<<<(EE + 255) / 256, 256>>>(dst, rowptr);
    // #4 GEMM layer 0 (+fused el/er) — ncu capture lands here
    {
        dim3 ggrid((NN + 127) / 128, 4);
        sgemm2_kernel<false, true><<<ggrid, 256>>>(feat, wcatL[0], z, lin, NN, 256, 128,
                                                   nullptr, nullptr, nullptr,
                                                   al[0], ar[0], el, er);
    }
    // #5-#8 finish CSR build
    scan_block_kernel<<<NB, 256>>>(rowptr, NSCAN, bsum);
    scan_bsum_kernel<<<1, 256>>>(bsum, NB);
    scan_add_fill_kernel<<<NB, 256>>>(rowptr, NSCAN, bsum, fill);
    scatter_kernel<<<(EE + 255) / 256, 256>>>(src, dst, fill, csrc);
    // #9 agg layer 0 (+fused BN stats)
    agg_kernel<32, false, true><<<NN / 8, 256>>>(rowptr, csrc, z, el, er, lin,
                                                 bc[0], nullptr, hbuf, bn);
    // #10 GEMM layer 1 (BN+ReLU fused in, el/er fused out)
    {
        dim3 ggrid((NN + 127) / 128, 4);
        sgemm2_kernel<true, true><<<ggrid, 256>>>(hbuf, wcatL[1], z, lin, NN, 256, 128,
                                                  bn, gg[0], bb[0], al[1], ar[1], el, er);
    }
    // #11 agg layer 1 (+fused BN stats)
    agg_kernel<32, false, true><<<NN / 8, 256>>>(rowptr, csrc, z, el, er, lin,
                                                 bc[1], nullptr, hbuf, bn + 256);
    // #12 GEMM layer 2 (BN+ReLU fused in)
    {
        dim3 ggrid((NN + 127) / 128, 5);
        sgemm2_kernel<true, false><<<ggrid, 256>>>(hbuf, wcatL[2], z, lin, NN, 320, 160,
                                                   bn + 256, gg[1], bb[1],
                                                   nullptr, nullptr, nullptr, nullptr);
    }
    // #13 el/er layer 2 (Dh=40)
    eler_kernel<<<(NN * 4 + 255) / 256, 256>>>(z, al[2], ar[2], el, er);
    // #14 agg layer 2 (head-mean epilogue)
    agg_kernel<40, true, false><<<NN / 8, 256>>>(rowptr, csrc, z, el, er, lin,
                                                 bc[2], bias_last, out, nullptr);
}